// round 12
// baseline (speedup 1.0000x reference)
#include <cuda_runtime.h>
#include <cuda_fp16.h>
#include <cuda_bf16.h>
#include <math.h>
#include <stdint.h>

#define BB 4
#define NQ 2304
#define NT 2312           // NQ + 8 summary tokens
#define CDIM 512
#define HH 8
#define DD 64
#define M1 (BB * NT)      // 9248
#define M3 (BB * NQ)      // 9216
#define QKV_ELEMS (BB * HH * NT * DD)   // 4,734,976
#define NKT 37            // ceil(NT/64) key tiles
#define LASTKT 36
#define NQT64 37          // ceil(NT/64) query tiles (64-query CTAs)
#define KVT (64 * 72)     // one K or V buffer in halves

// Scratch (no allocations allowed)
__device__ __half g_xh[M1 * CDIM];        // concat(X,S) fp16
__device__ __half g_wqkvh[CDIM * 1536];   // Wqkv fp16
__device__ __half g_wouth[CDIM * CDIM];   // Wout fp16
__device__ __half g_qh[QKV_ELEMS];        // normalized q fp16
__device__ __half g_kh[QKV_ELEMS];        // normalized k fp16
__device__ __half g_vh[QKV_ELEMS];        // v fp16
__device__ __half g_oh[QKV_ELEMS];        // attention output fp16

// ---------------------------------------------------------------------------
// helpers
// ---------------------------------------------------------------------------
static __device__ __forceinline__ uint32_t smem_u32(const void* p) {
    return (uint32_t)__cvta_generic_to_shared(p);
}

#define LDSM4(r0, r1, r2, r3, addr)                                            \
    asm volatile("ldmatrix.sync.aligned.m8n8.x4.shared.b16 {%0,%1,%2,%3}, [%4];" \
                 : "=r"(r0), "=r"(r1), "=r"(r2), "=r"(r3) : "r"(addr))

#define LDSM4T(r0, r1, r2, r3, addr)                                           \
    asm volatile("ldmatrix.sync.aligned.m8n8.x4.trans.shared.b16 {%0,%1,%2,%3}, [%4];" \
                 : "=r"(r0), "=r"(r1), "=r"(r2), "=r"(r3) : "r"(addr))

static __device__ __forceinline__ void mma_16816(
    float c[4], uint32_t a0, uint32_t a1, uint32_t a2, uint32_t a3,
    uint32_t b0, uint32_t b1)
{
    asm volatile(
        "mma.sync.aligned.m16n8k16.row.col.f32.f16.f16.f32 "
        "{%0,%1,%2,%3},{%4,%5,%6,%7},{%8,%9},{%0,%1,%2,%3};"
        : "+f"(c[0]), "+f"(c[1]), "+f"(c[2]), "+f"(c[3])
        : "r"(a0), "r"(a1), "r"(a2), "r"(a3), "r"(b0), "r"(b1));
}

static __device__ __forceinline__ uint32_t pack_half2(float x, float y) {
    __half2 h = __floats2half2_rn(x, y);
    return reinterpret_cast<uint32_t&>(h);
}

static __device__ __forceinline__ float ex2(float x) {
    float r;
    asm("ex2.approx.f32 %0, %1;" : "=f"(r) : "f"(x));
    return r;
}

#define CP_A16(dst, src, valid)                                                \
    asm volatile("cp.async.ca.shared.global [%0], [%1], 16, %2;"               \
                 :: "r"(dst), "l"(src), "r"((valid) ? 16 : 0))
#define CP_COMMIT() asm volatile("cp.async.commit_group;")
#define CP_WAIT1()  asm volatile("cp.async.wait_group 1;")
#define CP_WAIT0()  asm volatile("cp.async.wait_group 0;")

// ---------------------------------------------------------------------------
// Kernel 0: fp32 -> fp16 conversion of inputs (concat X,S) and weights.
// ---------------------------------------------------------------------------
#define CVT_A   (M1 * CDIM / 4)             // 1183744
#define CVT_WQ  (CDIM * 1536 / 4)           // 196608
#define CVT_WO  (CDIM * CDIM / 4)           // 65536
#define CVT_TOT (CVT_A + CVT_WQ + CVT_WO)   // 1445888

__global__ void __launch_bounds__(256) convert_kernel(
    const float* __restrict__ X, const float* __restrict__ S,
    const float* __restrict__ Wq, const float* __restrict__ Wo)
{
    int i = blockIdx.x * 256 + threadIdx.x;
    if (i >= CVT_TOT) return;
    const float* src;
    __half* dst;
    if (i < CVT_A) {
        int row = i >> 7;
        int c4 = (i & 127) * 4;
        int b = row / NT;
        int t = row - b * NT;
        src = (t < NQ) ? X + ((size_t)b * NQ + t) * CDIM + c4
                       : S + ((size_t)b * 8 + (t - NQ)) * CDIM + c4;
        dst = g_xh + (size_t)row * CDIM + c4;
    } else if (i < CVT_A + CVT_WQ) {
        int j = (i - CVT_A) * 4;
        src = Wq + j;
        dst = g_wqkvh + j;
    } else {
        int j = (i - CVT_A - CVT_WQ) * 4;
        src = Wo + j;
        dst = g_wouth + j;
    }
    float4 v = *(const float4*)src;
    __half2 h0 = __floats2half2_rn(v.x, v.y);
    __half2 h1 = __floats2half2_rn(v.z, v.w);
    uint2 u;
    u.x = reinterpret_cast<uint32_t&>(h0);
    u.y = reinterpret_cast<uint32_t&>(h1);
    *(uint2*)dst = u;
}

// ---------------------------------------------------------------------------
// Kernel 1: QKV GEMM, fp16 MMA + cp.async double buffer.
// Epilogue: fused L2-norm for q,k -> g_qh/g_kh; v -> g_vh.
// ---------------------------------------------------------------------------
__global__ void __launch_bounds__(256, 2) qkv_mma_kernel()
{
    __shared__ __half Ah[2][128][40];
    __shared__ __half Bh[2][32][136];

    const int m0 = blockIdx.y * 128;
    const int n0 = blockIdx.x * 128;
    const int tid = threadIdx.x;
    const int w = tid >> 5;
    const int lane = tid & 31;
    const int grp = lane >> 2;
    const int qd = lane & 3;
    const int wm = w >> 1;
    const int wn = w & 1;

    const int rowA = (lane & 7) + (((lane >> 3) & 1) << 3);
    const int colA = (lane >> 4) << 3;

    const int ar = tid >> 1;
    const int ac = (tid & 1) * 16;
    const bool aok = (m0 + ar) < M1;
    const int kr = tid >> 3;
    const int bc = (tid & 7) * 16;

#define QKV_PREF(kt, buf)                                                      \
    do {                                                                       \
        uint32_t ad = smem_u32(&Ah[buf][ar][ac]);                              \
        const __half* ag = g_xh + (size_t)(m0 + ar) * CDIM + (kt) * 32 + ac;   \
        CP_A16(ad, ag, aok);                                                   \
        CP_A16(ad + 16, ag + 8, aok);                                          \
        uint32_t bd = smem_u32(&Bh[buf][kr][bc]);                              \
        const __half* bg = g_wqkvh + (size_t)((kt) * 32 + kr) * 1536 + n0 + bc;\
        CP_A16(bd, bg, true);                                                  \
        CP_A16(bd + 16, bg + 8, true);                                         \
    } while (0)

    float acc[2][8][4];
#pragma unroll
    for (int i = 0; i < 2; i++)
#pragma unroll
        for (int j = 0; j < 8; j++)
#pragma unroll
            for (int r = 0; r < 4; r++) acc[i][j][r] = 0.0f;

    QKV_PREF(0, 0);
    CP_COMMIT();

    for (int kt = 0; kt < 16; kt++) {
        const int cur = kt & 1;
        if (kt < 15) {
            QKV_PREF(kt + 1, 1 - cur);
            CP_COMMIT();
            CP_WAIT1();
        } else {
            CP_WAIT0();
        }
        __syncthreads();
#pragma unroll
        for (int ks = 0; ks < 2; ks++) {
            uint32_t a[2][4];
#pragma unroll
            for (int mi = 0; mi < 2; mi++) {
                uint32_t addr = smem_u32(&Ah[cur][wm * 32 + mi * 16 + rowA][ks * 16 + colA]);
                LDSM4(a[mi][0], a[mi][1], a[mi][2], a[mi][3], addr);
            }
#pragma unroll
            for (int nc = 0; nc < 4; nc++) {
                uint32_t b0, b1, b2, b3;
                uint32_t addr = smem_u32(&Bh[cur][ks * 16 + rowA][wn * 64 + nc * 16 + colA]);
                LDSM4T(b0, b1, b2, b3, addr);
#pragma unroll
                for (int mi = 0; mi < 2; mi++) {
                    mma_16816(acc[mi][2 * nc],     a[mi][0], a[mi][1], a[mi][2], a[mi][3], b0, b1);
                    mma_16816(acc[mi][2 * nc + 1], a[mi][0], a[mi][1], a[mi][2], a[mi][3], b2, b3);
                }
            }
        }
        __syncthreads();
    }
#undef QKV_PREF

    // Epilogue. This warp's 64 columns = one head of one of q/k/v.
    const int cbase = n0 + wn * 64;
    const int which = cbase >> 9;          // 0=q 1=k 2=v (uniform per warp)
    const int h = (cbase >> 6) & 7;
    __half* dstbase = (which == 0) ? g_qh : (which == 1) ? g_kh : g_vh;

#pragma unroll
    for (int mi = 0; mi < 2; mi++) {
#pragma unroll
        for (int rr = 0; rr < 2; rr++) {
            int m = m0 + wm * 32 + mi * 16 + rr * 8 + grp;
            float inv = 1.0f;
            if (which < 2) {
                float ss = 0.0f;
#pragma unroll
                for (int nc = 0; nc < 8; nc++) {
                    float a0 = acc[mi][nc][rr * 2];
                    float a1 = acc[mi][nc][rr * 2 + 1];
                    ss += a0 * a0 + a1 * a1;
                }
                ss += __shfl_xor_sync(0xffffffffu, ss, 1);
                ss += __shfl_xor_sync(0xffffffffu, ss, 2);
                inv = 1.0f / fmaxf(sqrtf(ss), 1e-12f);
            }
            if (m < M1) {
                int b = m / NT;
                int t = m - b * NT;
                __half* dst = dstbase + (((size_t)b * HH + h) * NT + t) * DD;
#pragma unroll
                for (int nc = 0; nc < 8; nc++) {
                    *(__half2*)(dst + nc * 8 + qd * 2) = __floats2half2_rn(
                        acc[mi][nc][rr * 2] * inv, acc[mi][nc][rr * 2 + 1] * inv);
                }
            }
        }
    }
}

// ---------------------------------------------------------------------------
// Kernel 2: Flash attention, fp16 MMA + cp.async double-buffered K/V.
// 64-query tiles, 128 threads (4 warps), 4 CTAs/SM => exact 2-wave fit.
// Fixed-max softmax (q,k unit vectors => |score| <= 1).
// Each thread prefetches 32 halves (4 x 16B cp.async) per K and V row-half.
// ---------------------------------------------------------------------------
__global__ void __launch_bounds__(128, 4) attn_mma_kernel(const float* __restrict__ temp)
{
    extern __shared__ __half dynsm[];
    __half* Qs  = dynsm;                   // 64*72
    __half* Ksb = dynsm + 64 * 72;         // 2 * KVT
    __half* Vsb = Ksb + 2 * KVT;           // 2 * KVT

    const int bh = blockIdx.y;
    const int h = bh & (HH - 1);
    const int qt = blockIdx.x;
    const int tid = threadIdx.x;
    const int w = tid >> 5;                // 0..3
    const int lane = tid & 31;
    const int grp = lane >> 2;
    const int qd = lane & 3;
    const float T2 = temp[h] * 1.44269504089f;
    const float negM = -fabsf(T2) - 0.01f;

    const __half* qbase = g_qh + (size_t)bh * NT * DD;
    const __half* kbase = g_kh + (size_t)bh * NT * DD;
    const __half* vbase = g_vh + (size_t)bh * NT * DD;

    const int r_ = tid >> 1;           // 0..63
    const int cc_ = (tid & 1) * 32;    // 0 or 32 (halves)

#define ATT_PREF(kt, buf)                                                      \
    do {                                                                       \
        int jg = (kt) * 64 + r_;                                               \
        bool v = jg < NT;                                                      \
        const __half* kg = kbase + (size_t)jg * DD + cc_;                      \
        const __half* vg = vbase + (size_t)jg * DD + cc_;                      \
        uint32_t kd = smem_u32(Ksb + (buf) * KVT + r_ * 72 + cc_);             \
        uint32_t vd = smem_u32(Vsb + (buf) * KVT + r_ * 72 + cc_);             \
        CP_A16(kd,      kg,      v); CP_A16(kd + 16, kg + 8,  v);              \
        CP_A16(kd + 32, kg + 16, v); CP_A16(kd + 48, kg + 24, v);              \
        CP_A16(vd,      vg,      v); CP_A16(vd + 16, vg + 8,  v);              \
        CP_A16(vd + 32, vg + 16, v); CP_A16(vd + 48, vg + 24, v);              \
    } while (0)

    ATT_PREF(0, 0);
    CP_COMMIT();
    // stage Q tile (64 x 64)
#pragma unroll
    for (int it = 0; it < 4; it++) {
        int idx = it * 128 + tid;          // 0..511
        int r = idx >> 3;                  // 0..63
        int c8 = (idx & 7) * 8;
        int ig = qt * 64 + r;
        int4 val = make_int4(0, 0, 0, 0);
        if (ig < NT) val = *(const int4*)(qbase + (size_t)ig * DD + c8);
        *(int4*)(Qs + r * 72 + c8) = val;
    }
    __syncthreads();

    const int rowA = (lane & 7) + (((lane >> 3) & 1) << 3);
    const int colA = (lane >> 4) << 3;
    const int rowB = (lane & 7) + ((lane >> 4) << 3);
    const int colB = ((lane >> 3) & 1) << 3;

    uint32_t aq[4][4];
    {
        const int m0 = w * 16;
#pragma unroll
        for (int ks = 0; ks < 4; ks++) {
            uint32_t addr = smem_u32(Qs + (m0 + rowA) * 72 + ks * 16 + colA);
            LDSM4(aq[ks][0], aq[ks][1], aq[ks][2], aq[ks][3], addr);
        }
    }

    float o[8][4];
#pragma unroll
    for (int c = 0; c < 8; c++)
#pragma unroll
        for (int j = 0; j < 4; j++) o[c][j] = 0.0f;
    float l0 = 0.0f, l1 = 0.0f;

    for (int kt = 0; kt < NKT; kt++) {
        const int cur = kt & 1;
        if (kt < NKT - 1) {
            ATT_PREF(kt + 1, 1 - cur);
            CP_COMMIT();
            CP_WAIT1();
        } else {
            CP_WAIT0();
        }
        __syncthreads();

        const __half* Ks = Ksb + cur * KVT;
        const __half* Vs = Vsb + cur * KVT;

        float s[8][4];
#pragma unroll
        for (int c = 0; c < 8; c++)
#pragma unroll
            for (int j = 0; j < 4; j++) s[c][j] = 0.0f;

#pragma unroll
        for (int ks = 0; ks < 4; ks++) {
#pragma unroll
            for (int np = 0; np < 4; np++) {
                uint32_t b0, b1, b2, b3;
                uint32_t addr = smem_u32(Ks + (np * 16 + rowB) * 72 + ks * 16 + colB);
                LDSM4(b0, b1, b2, b3, addr);
                mma_16816(s[np * 2],     aq[ks][0], aq[ks][1], aq[ks][2], aq[ks][3], b0, b1);
                mma_16816(s[np * 2 + 1], aq[ks][0], aq[ks][1], aq[ks][2], aq[ks][3], b2, b3);
            }
        }

        // p = 2^(s*T2 - M); tail tile: only chunk 0 (8 keys) valid
        const bool lastk = (kt == LASTKT);
        uint32_t ph0[8], ph1[8];
#pragma unroll
        for (int c = 0; c < 8; c++) {
            float p00 = ex2(fmaf(s[c][0], T2, negM));
            float p01 = ex2(fmaf(s[c][1], T2, negM));
            float p10 = ex2(fmaf(s[c][2], T2, negM));
            float p11 = ex2(fmaf(s[c][3], T2, negM));
            if (lastk && c > 0) { p00 = p01 = p10 = p11 = 0.0f; }
            l0 += p00 + p01;
            l1 += p10 + p11;
            ph0[c] = pack_half2(p00, p01);
            ph1[c] = pack_half2(p10, p11);
        }

#pragma unroll
        for (int ks = 0; ks < 4; ks++) {
            uint32_t a0 = ph0[2 * ks], a1 = ph1[2 * ks];
            uint32_t a2 = ph0[2 * ks + 1], a3 = ph1[2 * ks + 1];
#pragma unroll
            for (int np = 0; np < 4; np++) {
                uint32_t b0, b1, b2, b3;
                uint32_t addr = smem_u32(Vs + (ks * 16 + rowA) * 72 + np * 16 + colA);
                LDSM4T(b0, b1, b2, b3, addr);
                mma_16816(o[np * 2],     a0, a1, a2, a3, b0, b1);
                mma_16816(o[np * 2 + 1], a0, a1, a2, a3, b2, b3);
            }
        }
        __syncthreads();
    }
#undef ATT_PREF

    // Epilogue: reduce row sums across the quad, normalize, write g_oh
    l0 += __shfl_xor_sync(0xffffffffu, l0, 1);
    l0 += __shfl_xor_sync(0xffffffffu, l0, 2);
    l1 += __shfl_xor_sync(0xffffffffu, l1, 1);
    l1 += __shfl_xor_sync(0xffffffffu, l1, 2);
    float inv0 = 1.0f / l0;
    float inv1 = 1.0f / l1;
    int t0 = qt * 64 + w * 16 + grp;
    if (t0 < NT) {
        __half* dst = g_oh + ((size_t)bh * NT + t0) * DD;
#pragma unroll
        for (int c = 0; c < 8; c++)
            *(__half2*)(dst + c * 8 + qd * 2) =
                __floats2half2_rn(o[c][0] * inv0, o[c][1] * inv0);
    }
    int t1 = t0 + 8;
    if (t1 < NT) {
        __half* dst = g_oh + ((size_t)bh * NT + t1) * DD;
#pragma unroll
        for (int c = 0; c < 8; c++)
            *(__half2*)(dst + c * 8 + qd * 2) =
                __floats2half2_rn(o[c][2] * inv1, o[c][3] * inv1);
    }
}

// ---------------------------------------------------------------------------
// Kernel 3: output projection, fp16 MMA + cp.async.
// ---------------------------------------------------------------------------
__global__ void __launch_bounds__(256, 2) out_mma_kernel(float* __restrict__ out)
{
    __shared__ __half Ah[2][128][40];
    __shared__ __half Bh[2][32][136];

    const int m0 = blockIdx.y * 128;
    const int n0 = blockIdx.x * 128;
    const int tid = threadIdx.x;
    const int w = tid >> 5;
    const int lane = tid & 31;
    const int grp = lane >> 2;
    const int qd = lane & 3;
    const int wm = w >> 1;
    const int wn = w & 1;

    const int rowA = (lane & 7) + (((lane >> 3) & 1) << 3);
    const int colA = (lane >> 4) << 3;

    const int ar = tid >> 1;
    const int ac = (tid & 1) * 16;
    const int am = m0 + ar;
    const int ab = am / NQ;
    const int at = am - ab * NQ;
    const int kr = tid >> 3;
    const int bc = (tid & 7) * 16;

#define OUT_PREF(kt, buf)                                                      \
    do {                                                                       \
        int k = (kt) * 32 + ac;                                                \
        int hh2 = k >> 6;                                                      \
        int dd2 = k & 63;                                                      \
        uint32_t ad = smem_u32(&Ah[buf][ar][ac]);                              \
        const __half* ag = g_oh + (((size_t)ab * HH + hh2) * NT + at) * DD + dd2; \
        CP_A16(ad, ag, true);                                                  \
        CP_A16(ad + 16, ag + 8, true);                                         \
        uint32_t bd = smem_u32(&Bh[buf][kr][bc]);                              \
        const __half* bg = g_wouth + (size_t)((kt) * 32 + kr) * CDIM + n0 + bc;\
        CP_A16(bd, bg, true);                                                  \
        CP_A16(bd + 16, bg + 8, true);                                         \
    } while (0)

    float acc[2][8][4];
#pragma unroll
    for (int i = 0; i < 2; i++)
#pragma unroll
        for (int j = 0; j < 8; j++)
#pragma unroll
            for (int r = 0; r < 4; r++) acc[i][j][r] = 0.0f;

    OUT_PREF(0, 0);
    CP_COMMIT();

    for (int kt = 0; kt < 16; kt++) {
        const int cur = kt & 1;
        if (kt < 15) {
            OUT_PREF(kt + 1, 1 - cur);
            CP_COMMIT();
            CP_WAIT1();
        } else {
            CP_WAIT0();
        }
        __syncthreads();
#pragma unroll
        for (int ks = 0; ks < 2; ks++) {
            uint32_t a[2][4];
#pragma unroll
            for (int mi = 0; mi < 2; mi++) {
                uint32_t addr = smem_u32(&Ah[cur][wm * 32 + mi * 16 + rowA][ks * 16 + colA]);
                LDSM4(a[mi][0], a[mi][1], a[mi][2], a[mi][3], addr);
            }
#pragma unroll
            for (int nc = 0; nc < 4; nc++) {
                uint32_t b0, b1, b2, b3;
                uint32_t addr = smem_u32(&Bh[cur][ks * 16 + rowA][wn * 64 + nc * 16 + colA]);
                LDSM4T(b0, b1, b2, b3, addr);
#pragma unroll
                for (int mi = 0; mi < 2; mi++) {
                    mma_16816(acc[mi][2 * nc],     a[mi][0], a[mi][1], a[mi][2], a[mi][3], b0, b1);
                    mma_16816(acc[mi][2 * nc + 1], a[mi][0], a[mi][1], a[mi][2], a[mi][3], b2, b3);
                }
            }
        }
        __syncthreads();
    }
#undef OUT_PREF

#pragma unroll
    for (int mi = 0; mi < 2; mi++) {
        int rbase = m0 + wm * 32 + mi * 16 + grp;
#pragma unroll
        for (int rr = 0; rr < 2; rr++) {
            int m = rbase + rr * 8;
            int b = m / NQ;
            int t = m - b * NQ;
            float* orow = out + ((size_t)b * NQ + t) * CDIM;
#pragma unroll
            for (int nc = 0; nc < 8; nc++) {
                int c = n0 + wn * 64 + nc * 8 + qd * 2;
                *(float2*)(orow + c) =
                    make_float2(acc[mi][nc][rr * 2], acc[mi][nc][rr * 2 + 1]);
            }
        }
    }
}

// ---------------------------------------------------------------------------
extern "C" void kernel_launch(void* const* d_in, const int* in_sizes, int n_in,
                              void* d_out, int out_size)
{
    const float* X    = (const float*)d_in[0];   // (4,2304,512)
    const float* S    = (const float*)d_in[1];   // (4,8,512)
    const float* Wqkv = (const float*)d_in[2];   // (512,1536)
    const float* Wout = (const float*)d_in[3];   // (512,512)
    const float* temp = (const float*)d_in[4];   // (8,1,1)
    float* out = (float*)d_out;                  // (4,2304,512)

    // 0. fp32 -> fp16 conversion
    {
        int blocks = (CVT_TOT + 255) / 256;
        convert_kernel<<<blocks, 256>>>(X, S, Wqkv, Wout);
    }
    // 1. QKV GEMM + fused l2norm epilogue
    {
        dim3 grid(1536 / 128, (M1 + 127) / 128);   // (12, 73)
        qkv_mma_kernel<<<grid, 256>>>();
    }
    // 2. Attention (64-query tiles, 4 CTAs/SM, exact 2-wave fit)
    {
        size_t smem = (64 * 72 + 4 * KVT) * sizeof(__half);    // 46080 B
        (void)cudaFuncSetAttribute(attn_mma_kernel,
                                   cudaFuncAttributeMaxDynamicSharedMemorySize,
                                   (int)smem);
        dim3 grid(NQT64, BB * HH);                 // (37, 32) = 1184 CTAs
        attn_mma_kernel<<<grid, 128, smem>>>(temp);
    }
    // 3. Output projection
    {
        dim3 grid(CDIM / 128, M3 / 128);           // (4, 72)
        out_mma_kernel<<<grid, 256>>>(out);
    }
}

// round 13
// speedup vs baseline: 1.0019x; 1.0019x over previous
#include <cuda_runtime.h>
#include <cuda_fp16.h>
#include <cuda_bf16.h>
#include <math.h>
#include <stdint.h>

#define BB 4
#define NQ 2304
#define NT 2312           // NQ + 8 summary tokens
#define CDIM 512
#define HH 8
#define DD 64
#define M1 (BB * NT)      // 9248
#define M3 (BB * NQ)      // 9216
#define QKV_ELEMS (BB * HH * NT * DD)   // 4,734,976
#define NKT 37            // ceil(NT/64) key tiles
#define LASTKT 36
#define NQT 19            // ceil(NT/128) query tiles
#define KVT (64 * 72)     // one K or V attention buffer in halves

// GEMM dynamic-smem layout (hal颗 units): Ah[2][128][72], Bh[2][64][136]
#define GA_STRIDE 72
#define GB_STRIDE 136
#define GA_SIZE (128 * GA_STRIDE)          // one A stage in halves
#define GB_SIZE (64 * GB_STRIDE)           // one B stage in halves
#define G_BH_OFF (2 * GA_SIZE)             // B base offset in halves
#define G_SMEM_BYTES ((2 * GA_SIZE + 2 * GB_SIZE) * 2)   // 71680 B

// Scratch (no allocations allowed)
__device__ __half g_xh[M1 * CDIM];        // concat(X,S) fp16
__device__ __half g_wqkvh[CDIM * 1536];   // Wqkv fp16
__device__ __half g_wouth[CDIM * CDIM];   // Wout fp16
__device__ __half g_qh[QKV_ELEMS];        // normalized q fp16
__device__ __half g_kh[QKV_ELEMS];        // normalized k fp16
__device__ __half g_vh[QKV_ELEMS];        // v fp16
__device__ __half g_oh[QKV_ELEMS];        // attention output fp16

// ---------------------------------------------------------------------------
// helpers
// ---------------------------------------------------------------------------
static __device__ __forceinline__ uint32_t smem_u32(const void* p) {
    return (uint32_t)__cvta_generic_to_shared(p);
}

#define LDSM4(r0, r1, r2, r3, addr)                                            \
    asm volatile("ldmatrix.sync.aligned.m8n8.x4.shared.b16 {%0,%1,%2,%3}, [%4];" \
                 : "=r"(r0), "=r"(r1), "=r"(r2), "=r"(r3) : "r"(addr))

#define LDSM4T(r0, r1, r2, r3, addr)                                           \
    asm volatile("ldmatrix.sync.aligned.m8n8.x4.trans.shared.b16 {%0,%1,%2,%3}, [%4];" \
                 : "=r"(r0), "=r"(r1), "=r"(r2), "=r"(r3) : "r"(addr))

static __device__ __forceinline__ void mma_16816(
    float c[4], uint32_t a0, uint32_t a1, uint32_t a2, uint32_t a3,
    uint32_t b0, uint32_t b1)
{
    asm volatile(
        "mma.sync.aligned.m16n8k16.row.col.f32.f16.f16.f32 "
        "{%0,%1,%2,%3},{%4,%5,%6,%7},{%8,%9},{%0,%1,%2,%3};"
        : "+f"(c[0]), "+f"(c[1]), "+f"(c[2]), "+f"(c[3])
        : "r"(a0), "r"(a1), "r"(a2), "r"(a3), "r"(b0), "r"(b1));
}

static __device__ __forceinline__ uint32_t pack_half2(float x, float y) {
    __half2 h = __floats2half2_rn(x, y);
    return reinterpret_cast<uint32_t&>(h);
}

static __device__ __forceinline__ float ex2(float x) {
    float r;
    asm("ex2.approx.f32 %0, %1;" : "=f"(r) : "f"(x));
    return r;
}

#define CP_A16(dst, src, valid)                                                \
    asm volatile("cp.async.ca.shared.global [%0], [%1], 16, %2;"               \
                 :: "r"(dst), "l"(src), "r"((valid) ? 16 : 0))
#define CP_COMMIT() asm volatile("cp.async.commit_group;")
#define CP_WAIT1()  asm volatile("cp.async.wait_group 1;")
#define CP_WAIT0()  asm volatile("cp.async.wait_group 0;")

// ---------------------------------------------------------------------------
// Kernel 0: fp32 -> fp16 conversion of inputs (concat X,S) and weights.
// ---------------------------------------------------------------------------
#define CVT_A   (M1 * CDIM / 4)             // 1183744
#define CVT_WQ  (CDIM * 1536 / 4)           // 196608
#define CVT_WO  (CDIM * CDIM / 4)           // 65536
#define CVT_TOT (CVT_A + CVT_WQ + CVT_WO)   // 1445888

__global__ void __launch_bounds__(256) convert_kernel(
    const float* __restrict__ X, const float* __restrict__ S,
    const float* __restrict__ Wq, const float* __restrict__ Wo)
{
    int i = blockIdx.x * 256 + threadIdx.x;
    if (i >= CVT_TOT) return;
    const float* src;
    __half* dst;
    if (i < CVT_A) {
        int row = i >> 7;
        int c4 = (i & 127) * 4;
        int b = row / NT;
        int t = row - b * NT;
        src = (t < NQ) ? X + ((size_t)b * NQ + t) * CDIM + c4
                       : S + ((size_t)b * 8 + (t - NQ)) * CDIM + c4;
        dst = g_xh + (size_t)row * CDIM + c4;
    } else if (i < CVT_A + CVT_WQ) {
        int j = (i - CVT_A) * 4;
        src = Wq + j;
        dst = g_wqkvh + j;
    } else {
        int j = (i - CVT_A - CVT_WQ) * 4;
        src = Wo + j;
        dst = g_wouth + j;
    }
    float4 v = *(const float4*)src;
    __half2 h0 = __floats2half2_rn(v.x, v.y);
    __half2 h1 = __floats2half2_rn(v.z, v.w);
    uint2 u;
    u.x = reinterpret_cast<uint32_t&>(h0);
    u.y = reinterpret_cast<uint32_t&>(h1);
    *(uint2*)dst = u;
}

// ---------------------------------------------------------------------------
// Kernel 1: QKV GEMM, fp16 MMA + cp.async, BK=64 (8 k-iters, half the syncs).
// Epilogue: fused L2-norm for q,k -> g_qh/g_kh; v -> g_vh.
// Dynamic smem: Ah[2][128][72] + Bh[2][64][136] = 71680 B.
// ---------------------------------------------------------------------------
__global__ void __launch_bounds__(256, 2) qkv_mma_kernel()
{
    extern __shared__ __half gsm[];
    __half* Ah = gsm;                 // [2][128][GA_STRIDE]
    __half* Bh = gsm + G_BH_OFF;      // [2][64][GB_STRIDE]

    const int m0 = blockIdx.y * 128;
    const int n0 = blockIdx.x * 128;
    const int tid = threadIdx.x;
    const int w = tid >> 5;
    const int lane = tid & 31;
    const int grp = lane >> 2;
    const int qd = lane & 3;
    const int wm = w >> 1;
    const int wn = w & 1;

    const int rowA = (lane & 7) + (((lane >> 3) & 1) << 3);
    const int colA = (lane >> 4) << 3;

    // A: 2 threads/row, each 32 halves (4x16B)
    const int ar = tid >> 1;
    const int ac = (tid & 1) * 32;
    const bool aok = (m0 + ar) < M1;
    // B: 4 threads/row, each 32 halves (4x16B)
    const int kr = tid >> 2;
    const int bc = (tid & 3) * 32;

#define QKV_PREF(kt, buf)                                                      \
    do {                                                                       \
        uint32_t ad = smem_u32(Ah + (buf) * GA_SIZE + ar * GA_STRIDE + ac);    \
        const __half* ag = g_xh + (size_t)(m0 + ar) * CDIM + (kt) * 64 + ac;   \
        CP_A16(ad,      ag,      aok); CP_A16(ad + 16, ag + 8,  aok);          \
        CP_A16(ad + 32, ag + 16, aok); CP_A16(ad + 48, ag + 24, aok);          \
        uint32_t bd = smem_u32(Bh + (buf) * GB_SIZE + kr * GB_STRIDE + bc);    \
        const __half* bg = g_wqkvh + (size_t)((kt) * 64 + kr) * 1536 + n0 + bc;\
        CP_A16(bd,      bg,      true); CP_A16(bd + 16, bg + 8,  true);        \
        CP_A16(bd + 32, bg + 16, true); CP_A16(bd + 48, bg + 24, true);        \
    } while (0)

    float acc[2][8][4];
#pragma unroll
    for (int i = 0; i < 2; i++)
#pragma unroll
        for (int j = 0; j < 8; j++)
#pragma unroll
            for (int r = 0; r < 4; r++) acc[i][j][r] = 0.0f;

    QKV_PREF(0, 0);
    CP_COMMIT();

    for (int kt = 0; kt < 8; kt++) {
        const int cur = kt & 1;
        if (kt < 7) {
            QKV_PREF(kt + 1, 1 - cur);
            CP_COMMIT();
            CP_WAIT1();
        } else {
            CP_WAIT0();
        }
        __syncthreads();
        const __half* Ac = Ah + cur * GA_SIZE;
        const __half* Bc = Bh + cur * GB_SIZE;
#pragma unroll
        for (int ks = 0; ks < 4; ks++) {
            uint32_t a[2][4];
#pragma unroll
            for (int mi = 0; mi < 2; mi++) {
                uint32_t addr = smem_u32(Ac + (wm * 32 + mi * 16 + rowA) * GA_STRIDE + ks * 16 + colA);
                LDSM4(a[mi][0], a[mi][1], a[mi][2], a[mi][3], addr);
            }
#pragma unroll
            for (int nc = 0; nc < 4; nc++) {
                uint32_t b0, b1, b2, b3;
                uint32_t addr = smem_u32(Bc + (ks * 16 + rowA) * GB_STRIDE + wn * 64 + nc * 16 + colA);
                LDSM4T(b0, b1, b2, b3, addr);
#pragma unroll
                for (int mi = 0; mi < 2; mi++) {
                    mma_16816(acc[mi][2 * nc],     a[mi][0], a[mi][1], a[mi][2], a[mi][3], b0, b1);
                    mma_16816(acc[mi][2 * nc + 1], a[mi][0], a[mi][1], a[mi][2], a[mi][3], b2, b3);
                }
            }
        }
        __syncthreads();
    }
#undef QKV_PREF

    // Epilogue. This warp's 64 columns = one head of one of q/k/v.
    const int cbase = n0 + wn * 64;
    const int which = cbase >> 9;          // 0=q 1=k 2=v (uniform per warp)
    const int h = (cbase >> 6) & 7;
    __half* dstbase = (which == 0) ? g_qh : (which == 1) ? g_kh : g_vh;

#pragma unroll
    for (int mi = 0; mi < 2; mi++) {
#pragma unroll
        for (int rr = 0; rr < 2; rr++) {
            int m = m0 + wm * 32 + mi * 16 + rr * 8 + grp;
            float inv = 1.0f;
            if (which < 2) {
                float ss = 0.0f;
#pragma unroll
                for (int nc = 0; nc < 8; nc++) {
                    float a0 = acc[mi][nc][rr * 2];
                    float a1 = acc[mi][nc][rr * 2 + 1];
                    ss += a0 * a0 + a1 * a1;
                }
                ss += __shfl_xor_sync(0xffffffffu, ss, 1);
                ss += __shfl_xor_sync(0xffffffffu, ss, 2);
                inv = 1.0f / fmaxf(sqrtf(ss), 1e-12f);
            }
            if (m < M1) {
                int b = m / NT;
                int t = m - b * NT;
                __half* dst = dstbase + (((size_t)b * HH + h) * NT + t) * DD;
#pragma unroll
                for (int nc = 0; nc < 8; nc++) {
                    *(__half2*)(dst + nc * 8 + qd * 2) = __floats2half2_rn(
                        acc[mi][nc][rr * 2] * inv, acc[mi][nc][rr * 2 + 1] * inv);
                }
            }
        }
    }
}

// ---------------------------------------------------------------------------
// Kernel 2: Flash attention (round-9 proven version, byte-identical).
// 128-query tiles, 256 threads, fixed-max softmax, double-buffered K/V.
// ---------------------------------------------------------------------------
__global__ void __launch_bounds__(256, 2) attn_mma_kernel(const float* __restrict__ temp)
{
    extern __shared__ __half dynsm[];
    __half* Qs  = dynsm;                   // 128*72
    __half* Ksb = dynsm + 128 * 72;        // 2 * KVT
    __half* Vsb = Ksb + 2 * KVT;           // 2 * KVT

    const int bh = blockIdx.y;
    const int h = bh & (HH - 1);
    const int qt = blockIdx.x;
    const int tid = threadIdx.x;
    const int w = tid >> 5;
    const int lane = tid & 31;
    const int grp = lane >> 2;
    const int qd = lane & 3;
    const float T2 = temp[h] * 1.44269504089f;
    const float negM = -fabsf(T2) - 0.01f;

    const __half* qbase = g_qh + (size_t)bh * NT * DD;
    const __half* kbase = g_kh + (size_t)bh * NT * DD;
    const __half* vbase = g_vh + (size_t)bh * NT * DD;

    const int r_ = tid >> 2;           // 0..63
    const int cc_ = (tid & 3) * 16;    // 0,16,32,48

#define ATT_PREF(kt, buf)                                                      \
    do {                                                                       \
        int jg = (kt) * 64 + r_;                                               \
        bool v = jg < NT;                                                      \
        const __half* kg = kbase + (size_t)jg * DD + cc_;                      \
        const __half* vg = vbase + (size_t)jg * DD + cc_;                      \
        uint32_t kd = smem_u32(Ksb + (buf) * KVT + r_ * 72 + cc_);             \
        uint32_t vd = smem_u32(Vsb + (buf) * KVT + r_ * 72 + cc_);             \
        CP_A16(kd, kg, v); CP_A16(kd + 16, kg + 8, v);                         \
        CP_A16(vd, vg, v); CP_A16(vd + 16, vg + 8, v);                         \
    } while (0)

    ATT_PREF(0, 0);
    CP_COMMIT();
#pragma unroll
    for (int it = 0; it < 4; it++) {
        int idx = it * 256 + tid;
        int r = idx >> 3;
        int c8 = (idx & 7) * 8;
        int ig = qt * 128 + r;
        int4 val = make_int4(0, 0, 0, 0);
        if (ig < NT) val = *(const int4*)(qbase + (size_t)ig * DD + c8);
        *(int4*)(Qs + r * 72 + c8) = val;
    }
    __syncthreads();

    const int rowA = (lane & 7) + (((lane >> 3) & 1) << 3);
    const int colA = (lane >> 4) << 3;
    const int rowB = (lane & 7) + ((lane >> 4) << 3);
    const int colB = ((lane >> 3) & 1) << 3;

    uint32_t aq[4][4];
    {
        const int m0 = w * 16;
#pragma unroll
        for (int ks = 0; ks < 4; ks++) {
            uint32_t addr = smem_u32(Qs + (m0 + rowA) * 72 + ks * 16 + colA);
            LDSM4(aq[ks][0], aq[ks][1], aq[ks][2], aq[ks][3], addr);
        }
    }

    float o[8][4];
#pragma unroll
    for (int c = 0; c < 8; c++)
#pragma unroll
        for (int j = 0; j < 4; j++) o[c][j] = 0.0f;
    float l0 = 0.0f, l1 = 0.0f;

    for (int kt = 0; kt < NKT; kt++) {
        const int cur = kt & 1;
        if (kt < NKT - 1) {
            ATT_PREF(kt + 1, 1 - cur);
            CP_COMMIT();
            CP_WAIT1();
        } else {
            CP_WAIT0();
        }
        __syncthreads();

        const __half* Ks = Ksb + cur * KVT;
        const __half* Vs = Vsb + cur * KVT;

        float s[8][4];
#pragma unroll
        for (int c = 0; c < 8; c++)
#pragma unroll
            for (int j = 0; j < 4; j++) s[c][j] = 0.0f;

#pragma unroll
        for (int ks = 0; ks < 4; ks++) {
#pragma unroll
            for (int np = 0; np < 4; np++) {
                uint32_t b0, b1, b2, b3;
                uint32_t addr = smem_u32(Ks + (np * 16 + rowB) * 72 + ks * 16 + colB);
                LDSM4(b0, b1, b2, b3, addr);
                mma_16816(s[np * 2],     aq[ks][0], aq[ks][1], aq[ks][2], aq[ks][3], b0, b1);
                mma_16816(s[np * 2 + 1], aq[ks][0], aq[ks][1], aq[ks][2], aq[ks][3], b2, b3);
            }
        }

        // p = 2^(s*T2 - M); tail tile: only chunk 0 (8 keys) valid
        const bool lastk = (kt == LASTKT);
        uint32_t ph0[8], ph1[8];
#pragma unroll
        for (int c = 0; c < 8; c++) {
            float p00 = ex2(fmaf(s[c][0], T2, negM));
            float p01 = ex2(fmaf(s[c][1], T2, negM));
            float p10 = ex2(fmaf(s[c][2], T2, negM));
            float p11 = ex2(fmaf(s[c][3], T2, negM));
            if (lastk && c > 0) { p00 = p01 = p10 = p11 = 0.0f; }
            l0 += p00 + p01;
            l1 += p10 + p11;
            ph0[c] = pack_half2(p00, p01);
            ph1[c] = pack_half2(p10, p11);
        }

#pragma unroll
        for (int ks = 0; ks < 4; ks++) {
            uint32_t a0 = ph0[2 * ks], a1 = ph1[2 * ks];
            uint32_t a2 = ph0[2 * ks + 1], a3 = ph1[2 * ks + 1];
#pragma unroll
            for (int np = 0; np < 4; np++) {
                uint32_t b0, b1, b2, b3;
                uint32_t addr = smem_u32(Vs + (ks * 16 + rowA) * 72 + np * 16 + colA);
                LDSM4T(b0, b1, b2, b3, addr);
                mma_16816(o[np * 2],     a0, a1, a2, a3, b0, b1);
                mma_16816(o[np * 2 + 1], a0, a1, a2, a3, b2, b3);
            }
        }
        __syncthreads();
    }
#undef ATT_PREF

    // Epilogue: reduce row sums across the quad, normalize, write g_oh
    l0 += __shfl_xor_sync(0xffffffffu, l0, 1);
    l0 += __shfl_xor_sync(0xffffffffu, l0, 2);
    l1 += __shfl_xor_sync(0xffffffffu, l1, 1);
    l1 += __shfl_xor_sync(0xffffffffu, l1, 2);
    float inv0 = 1.0f / l0;
    float inv1 = 1.0f / l1;
    int t0 = qt * 128 + w * 16 + grp;
    if (t0 < NT) {
        __half* dst = g_oh + ((size_t)bh * NT + t0) * DD;
#pragma unroll
        for (int c = 0; c < 8; c++)
            *(__half2*)(dst + c * 8 + qd * 2) =
                __floats2half2_rn(o[c][0] * inv0, o[c][1] * inv0);
    }
    int t1 = t0 + 8;
    if (t1 < NT) {
        __half* dst = g_oh + ((size_t)bh * NT + t1) * DD;
#pragma unroll
        for (int c = 0; c < 8; c++)
            *(__half2*)(dst + c * 8 + qd * 2) =
                __floats2half2_rn(o[c][2] * inv1, o[c][3] * inv1);
    }
}

// ---------------------------------------------------------------------------
// Kernel 3: output projection, fp16 MMA + cp.async, BK=64.
// A chunk kt = head kt of g_oh (contiguous d). Dynamic smem as qkv.
// ---------------------------------------------------------------------------
__global__ void __launch_bounds__(256, 2) out_mma_kernel(float* __restrict__ out)
{
    extern __shared__ __half gsm[];
    __half* Ah = gsm;
    __half* Bh = gsm + G_BH_OFF;

    const int m0 = blockIdx.y * 128;
    const int n0 = blockIdx.x * 128;
    const int tid = threadIdx.x;
    const int w = tid >> 5;
    const int lane = tid & 31;
    const int grp = lane >> 2;
    const int qd = lane & 3;
    const int wm = w >> 1;
    const int wn = w & 1;

    const int rowA = (lane & 7) + (((lane >> 3) & 1) << 3);
    const int colA = (lane >> 4) << 3;

    const int ar = tid >> 1;
    const int ac = (tid & 1) * 32;
    const int am = m0 + ar;
    const int ab = am / NQ;
    const int at = am - ab * NQ;
    const int kr = tid >> 2;
    const int bc = (tid & 3) * 32;

#define OUT_PREF(kt, buf)                                                      \
    do {                                                                       \
        uint32_t ad = smem_u32(Ah + (buf) * GA_SIZE + ar * GA_STRIDE + ac);    \
        const __half* ag = g_oh + (((size_t)ab * HH + (kt)) * NT + at) * DD + ac; \
        CP_A16(ad,      ag,      true); CP_A16(ad + 16, ag + 8,  true);        \
        CP_A16(ad + 32, ag + 16, true); CP_A16(ad + 48, ag + 24, true);        \
        uint32_t bd = smem_u32(Bh + (buf) * GB_SIZE + kr * GB_STRIDE + bc);    \
        const __half* bg = g_wouth + (size_t)((kt) * 64 + kr) * CDIM + n0 + bc;\
        CP_A16(bd,      bg,      true); CP_A16(bd + 16, bg + 8,  true);        \
        CP_A16(bd + 32, bg + 16, true); CP_A16(bd + 48, bg + 24, true);        \
    } while (0)

    float acc[2][8][4];
#pragma unroll
    for (int i = 0; i < 2; i++)
#pragma unroll
        for (int j = 0; j < 8; j++)
#pragma unroll
            for (int r = 0; r < 4; r++) acc[i][j][r] = 0.0f;

    OUT_PREF(0, 0);
    CP_COMMIT();

    for (int kt = 0; kt < 8; kt++) {
        const int cur = kt & 1;
        if (kt < 7) {
            OUT_PREF(kt + 1, 1 - cur);
            CP_COMMIT();
            CP_WAIT1();
        } else {
            CP_WAIT0();
        }
        __syncthreads();
        const __half* Ac = Ah + cur * GA_SIZE;
        const __half* Bc = Bh + cur * GB_SIZE;
#pragma unroll
        for (int ks = 0; ks < 4; ks++) {
            uint32_t a[2][4];
#pragma unroll
            for (int mi = 0; mi < 2; mi++) {
                uint32_t addr = smem_u32(Ac + (wm * 32 + mi * 16 + rowA) * GA_STRIDE + ks * 16 + colA);
                LDSM4(a[mi][0], a[mi][1], a[mi][2], a[mi][3], addr);
            }
#pragma unroll
            for (int nc = 0; nc < 4; nc++) {
                uint32_t b0, b1, b2, b3;
                uint32_t addr = smem_u32(Bc + (ks * 16 + rowA) * GB_STRIDE + wn * 64 + nc * 16 + colA);
                LDSM4T(b0, b1, b2, b3, addr);
#pragma unroll
                for (int mi = 0; mi < 2; mi++) {
                    mma_16816(acc[mi][2 * nc],     a[mi][0], a[mi][1], a[mi][2], a[mi][3], b0, b1);
                    mma_16816(acc[mi][2 * nc + 1], a[mi][0], a[mi][1], a[mi][2], a[mi][3], b2, b3);
                }
            }
        }
        __syncthreads();
    }
#undef OUT_PREF

#pragma unroll
    for (int mi = 0; mi < 2; mi++) {
        int rbase = m0 + wm * 32 + mi * 16 + grp;
#pragma unroll
        for (int rr = 0; rr < 2; rr++) {
            int m = rbase + rr * 8;
            int b = m / NQ;
            int t = m - b * NQ;
            float* orow = out + ((size_t)b * NQ + t) * CDIM;
#pragma unroll
            for (int nc = 0; nc < 8; nc++) {
                int c = n0 + wn * 64 + nc * 8 + qd * 2;
                *(float2*)(orow + c) =
                    make_float2(acc[mi][nc][rr * 2], acc[mi][nc][rr * 2 + 1]);
            }
        }
    }
}

// ---------------------------------------------------------------------------
extern "C" void kernel_launch(void* const* d_in, const int* in_sizes, int n_in,
                              void* d_out, int out_size)
{
    const float* X    = (const float*)d_in[0];   // (4,2304,512)
    const float* S    = (const float*)d_in[1];   // (4,8,512)
    const float* Wqkv = (const float*)d_in[2];   // (512,1536)
    const float* Wout = (const float*)d_in[3];   // (512,512)
    const float* temp = (const float*)d_in[4];   // (8,1,1)
    float* out = (float*)d_out;                  // (4,2304,512)

    // 0. fp32 -> fp16 conversion
    {
        int blocks = (CVT_TOT + 255) / 256;
        convert_kernel<<<blocks, 256>>>(X, S, Wqkv, Wout);
    }
    // 1. QKV GEMM + fused l2norm epilogue (BK=64)
    {
        (void)cudaFuncSetAttribute(qkv_mma_kernel,
                                   cudaFuncAttributeMaxDynamicSharedMemorySize,
                                   G_SMEM_BYTES);
        dim3 grid(1536 / 128, (M1 + 127) / 128);   // (12, 73)
        qkv_mma_kernel<<<grid, 256, G_SMEM_BYTES>>>();
    }
    // 2. Attention (round-9 config: 128-query tiles, 256 threads)
    {
        size_t smem = (128 * 72 + 4 * KVT) * sizeof(__half);   // 55296 B
        (void)cudaFuncSetAttribute(attn_mma_kernel,
                                   cudaFuncAttributeMaxDynamicSharedMemorySize,
                                   (int)smem);
        dim3 grid(NQT, BB * HH);                   // (19, 32)
        attn_mma_kernel<<<grid, 256, smem>>>(temp);
    }
    // 3. Output projection (BK=64)
    {
        (void)cudaFuncSetAttribute(out_mma_kernel,
                                   cudaFuncAttributeMaxDynamicSharedMemorySize,
                                   G_SMEM_BYTES);
        dim3 grid(CDIM / 128, M3 / 128);           // (4, 72)
        out_mma_kernel<<<grid, 256, G_SMEM_BYTES>>>(out);
    }
}

// round 14
// speedup vs baseline: 1.0210x; 1.0191x over previous
#include <cuda_runtime.h>
#include <cuda_fp16.h>
#include <cuda_bf16.h>
#include <math.h>
#include <stdint.h>

#define BB 4
#define NQ 2304
#define NT 2312           // NQ + 8 summary tokens
#define CDIM 512
#define HH 8
#define DD 64
#define M1 (BB * NT)      // 9248
#define M3 (BB * NQ)      // 9216
#define QKV_ELEMS (BB * HH * NT * DD)   // 4,734,976
#define NKT 37            // ceil(NT/64) key tiles
#define LASTKT 36
#define NQT 19            // ceil(NT/128) query tiles
#define KVT (64 * 72)     // one K or V buffer in halves
#define ONES16X2 0x3C003C00u   // half2(1.0, 1.0)

// Scratch (no allocations allowed)
__device__ __half g_xh[M1 * CDIM];        // concat(X,S) fp16
__device__ __half g_wqkvh[CDIM * 1536];   // Wqkv fp16
__device__ __half g_wouth[CDIM * CDIM];   // Wout fp16
__device__ __half g_qh[QKV_ELEMS];        // normalized q fp16
__device__ __half g_kh[QKV_ELEMS];        // normalized k fp16
__device__ __half g_vh[QKV_ELEMS];        // v fp16
__device__ __half g_oh[QKV_ELEMS];        // attention output fp16

// ---------------------------------------------------------------------------
// helpers
// ---------------------------------------------------------------------------
static __device__ __forceinline__ uint32_t smem_u32(const void* p) {
    return (uint32_t)__cvta_generic_to_shared(p);
}

#define LDSM4(r0, r1, r2, r3, addr)                                            \
    asm volatile("ldmatrix.sync.aligned.m8n8.x4.shared.b16 {%0,%1,%2,%3}, [%4];" \
                 : "=r"(r0), "=r"(r1), "=r"(r2), "=r"(r3) : "r"(addr))

#define LDSM4T(r0, r1, r2, r3, addr)                                           \
    asm volatile("ldmatrix.sync.aligned.m8n8.x4.trans.shared.b16 {%0,%1,%2,%3}, [%4];" \
                 : "=r"(r0), "=r"(r1), "=r"(r2), "=r"(r3) : "r"(addr))

static __device__ __forceinline__ void mma_16816(
    float c[4], uint32_t a0, uint32_t a1, uint32_t a2, uint32_t a3,
    uint32_t b0, uint32_t b1)
{
    asm volatile(
        "mma.sync.aligned.m16n8k16.row.col.f32.f16.f16.f32 "
        "{%0,%1,%2,%3},{%4,%5,%6,%7},{%8,%9},{%0,%1,%2,%3};"
        : "+f"(c[0]), "+f"(c[1]), "+f"(c[2]), "+f"(c[3])
        : "r"(a0), "r"(a1), "r"(a2), "r"(a3), "r"(b0), "r"(b1));
}

// pack two fp32 into f16x2 (lo = x, hi = y)
static __device__ __forceinline__ uint32_t cvt_f16x2(float x, float y) {
    uint32_t r;
    asm("cvt.rn.f16x2.f32 %0, %1, %2;" : "=r"(r) : "f"(y), "f"(x));
    return r;
}
static __device__ __forceinline__ uint32_t ex2_f16x2(uint32_t a) {
    uint32_t r;
    asm("ex2.approx.f16x2 %0, %1;" : "=r"(r) : "r"(a));
    return r;
}

#define CP_A16(dst, src, valid)                                                \
    asm volatile("cp.async.ca.shared.global [%0], [%1], 16, %2;"               \
                 :: "r"(dst), "l"(src), "r"((valid) ? 16 : 0))
#define CP_COMMIT() asm volatile("cp.async.commit_group;")
#define CP_WAIT1()  asm volatile("cp.async.wait_group 1;")
#define CP_WAIT0()  asm volatile("cp.async.wait_group 0;")

// ---------------------------------------------------------------------------
// Kernel 0: fp32 -> fp16 conversion of inputs (concat X,S) and weights.
// ---------------------------------------------------------------------------
#define CVT_A   (M1 * CDIM / 4)             // 1183744
#define CVT_WQ  (CDIM * 1536 / 4)           // 196608
#define CVT_WO  (CDIM * CDIM / 4)           // 65536
#define CVT_TOT (CVT_A + CVT_WQ + CVT_WO)   // 1445888

__global__ void __launch_bounds__(256) convert_kernel(
    const float* __restrict__ X, const float* __restrict__ S,
    const float* __restrict__ Wq, const float* __restrict__ Wo)
{
    int i = blockIdx.x * 256 + threadIdx.x;
    if (i >= CVT_TOT) return;
    const float* src;
    __half* dst;
    if (i < CVT_A) {
        int row = i >> 7;
        int c4 = (i & 127) * 4;
        int b = row / NT;
        int t = row - b * NT;
        src = (t < NQ) ? X + ((size_t)b * NQ + t) * CDIM + c4
                       : S + ((size_t)b * 8 + (t - NQ)) * CDIM + c4;
        dst = g_xh + (size_t)row * CDIM + c4;
    } else if (i < CVT_A + CVT_WQ) {
        int j = (i - CVT_A) * 4;
        src = Wq + j;
        dst = g_wqkvh + j;
    } else {
        int j = (i - CVT_A - CVT_WQ) * 4;
        src = Wo + j;
        dst = g_wouth + j;
    }
    float4 v = *(const float4*)src;
    __half2 h0 = __floats2half2_rn(v.x, v.y);
    __half2 h1 = __floats2half2_rn(v.z, v.w);
    uint2 u;
    u.x = reinterpret_cast<uint32_t&>(h0);
    u.y = reinterpret_cast<uint32_t&>(h1);
    *(uint2*)dst = u;
}

// ---------------------------------------------------------------------------
// Kernel 1: QKV GEMM (round-9 proven BK=32 version).
// Epilogue: fused L2-norm for q,k -> g_qh/g_kh; v -> g_vh.
// ---------------------------------------------------------------------------
__global__ void __launch_bounds__(256, 2) qkv_mma_kernel()
{
    __shared__ __half Ah[2][128][40];
    __shared__ __half Bh[2][32][136];

    const int m0 = blockIdx.y * 128;
    const int n0 = blockIdx.x * 128;
    const int tid = threadIdx.x;
    const int w = tid >> 5;
    const int lane = tid & 31;
    const int grp = lane >> 2;
    const int qd = lane & 3;
    const int wm = w >> 1;
    const int wn = w & 1;

    const int rowA = (lane & 7) + (((lane >> 3) & 1) << 3);
    const int colA = (lane >> 4) << 3;

    const int ar = tid >> 1;
    const int ac = (tid & 1) * 16;
    const bool aok = (m0 + ar) < M1;
    const int kr = tid >> 3;
    const int bc = (tid & 7) * 16;

#define QKV_PREF(kt, buf)                                                      \
    do {                                                                       \
        uint32_t ad = smem_u32(&Ah[buf][ar][ac]);                              \
        const __half* ag = g_xh + (size_t)(m0 + ar) * CDIM + (kt) * 32 + ac;   \
        CP_A16(ad, ag, aok);                                                   \
        CP_A16(ad + 16, ag + 8, aok);                                          \
        uint32_t bd = smem_u32(&Bh[buf][kr][bc]);                              \
        const __half* bg = g_wqkvh + (size_t)((kt) * 32 + kr) * 1536 + n0 + bc;\
        CP_A16(bd, bg, true);                                                  \
        CP_A16(bd + 16, bg + 8, true);                                         \
    } while (0)

    float acc[2][8][4];
#pragma unroll
    for (int i = 0; i < 2; i++)
#pragma unroll
        for (int j = 0; j < 8; j++)
#pragma unroll
            for (int r = 0; r < 4; r++) acc[i][j][r] = 0.0f;

    QKV_PREF(0, 0);
    CP_COMMIT();

    for (int kt = 0; kt < 16; kt++) {
        const int cur = kt & 1;
        if (kt < 15) {
            QKV_PREF(kt + 1, 1 - cur);
            CP_COMMIT();
            CP_WAIT1();
        } else {
            CP_WAIT0();
        }
        __syncthreads();
#pragma unroll
        for (int ks = 0; ks < 2; ks++) {
            uint32_t a[2][4];
#pragma unroll
            for (int mi = 0; mi < 2; mi++) {
                uint32_t addr = smem_u32(&Ah[cur][wm * 32 + mi * 16 + rowA][ks * 16 + colA]);
                LDSM4(a[mi][0], a[mi][1], a[mi][2], a[mi][3], addr);
            }
#pragma unroll
            for (int nc = 0; nc < 4; nc++) {
                uint32_t b0, b1, b2, b3;
                uint32_t addr = smem_u32(&Bh[cur][ks * 16 + rowA][wn * 64 + nc * 16 + colA]);
                LDSM4T(b0, b1, b2, b3, addr);
#pragma unroll
                for (int mi = 0; mi < 2; mi++) {
                    mma_16816(acc[mi][2 * nc],     a[mi][0], a[mi][1], a[mi][2], a[mi][3], b0, b1);
                    mma_16816(acc[mi][2 * nc + 1], a[mi][0], a[mi][1], a[mi][2], a[mi][3], b2, b3);
                }
            }
        }
        __syncthreads();
    }
#undef QKV_PREF

    const int cbase = n0 + wn * 64;
    const int which = cbase >> 9;
    const int h = (cbase >> 6) & 7;
    __half* dstbase = (which == 0) ? g_qh : (which == 1) ? g_kh : g_vh;

#pragma unroll
    for (int mi = 0; mi < 2; mi++) {
#pragma unroll
        for (int rr = 0; rr < 2; rr++) {
            int m = m0 + wm * 32 + mi * 16 + rr * 8 + grp;
            float inv = 1.0f;
            if (which < 2) {
                float ss = 0.0f;
#pragma unroll
                for (int nc = 0; nc < 8; nc++) {
                    float a0 = acc[mi][nc][rr * 2];
                    float a1 = acc[mi][nc][rr * 2 + 1];
                    ss += a0 * a0 + a1 * a1;
                }
                ss += __shfl_xor_sync(0xffffffffu, ss, 1);
                ss += __shfl_xor_sync(0xffffffffu, ss, 2);
                inv = 1.0f / fmaxf(sqrtf(ss), 1e-12f);
            }
            if (m < M1) {
                int b = m / NT;
                int t = m - b * NT;
                __half* dst = dstbase + (((size_t)b * HH + h) * NT + t) * DD;
#pragma unroll
                for (int nc = 0; nc < 8; nc++) {
                    *(__half2*)(dst + nc * 8 + qd * 2) = __floats2half2_rn(
                        acc[mi][nc][rr * 2] * inv, acc[mi][nc][rr * 2 + 1] * inv);
                }
            }
        }
    }
}

// ---------------------------------------------------------------------------
// Kernel 2: Flash attention. Round-9 structure + f16x2 ex2 (half the MUFU)
// + l computed by ones-MMA (no serial adds, no shuffles).
// ---------------------------------------------------------------------------
__global__ void __launch_bounds__(256, 2) attn_mma_kernel(const float* __restrict__ temp)
{
    extern __shared__ __half dynsm[];
    __half* Qs  = dynsm;                   // 128*72
    __half* Ksb = dynsm + 128 * 72;        // 2 * KVT
    __half* Vsb = Ksb + 2 * KVT;           // 2 * KVT

    const int bh = blockIdx.y;
    const int h = bh & (HH - 1);
    const int qt = blockIdx.x;
    const int tid = threadIdx.x;
    const int w = tid >> 5;
    const int lane = tid & 31;
    const int grp = lane >> 2;
    const int qd = lane & 3;
    const float T2 = temp[h] * 1.44269504089f;
    const float negM = -fabsf(T2) - 0.01f;

    const __half* qbase = g_qh + (size_t)bh * NT * DD;
    const __half* kbase = g_kh + (size_t)bh * NT * DD;
    const __half* vbase = g_vh + (size_t)bh * NT * DD;

    const int r_ = tid >> 2;           // 0..63
    const int cc_ = (tid & 3) * 16;    // 0,16,32,48

#define ATT_PREF(kt, buf)                                                      \
    do {                                                                       \
        int jg = (kt) * 64 + r_;                                               \
        bool v = jg < NT;                                                      \
        const __half* kg = kbase + (size_t)jg * DD + cc_;                      \
        const __half* vg = vbase + (size_t)jg * DD + cc_;                      \
        uint32_t kd = smem_u32(Ksb + (buf) * KVT + r_ * 72 + cc_);             \
        uint32_t vd = smem_u32(Vsb + (buf) * KVT + r_ * 72 + cc_);             \
        CP_A16(kd, kg, v); CP_A16(kd + 16, kg + 8, v);                         \
        CP_A16(vd, vg, v); CP_A16(vd + 16, vg + 8, v);                         \
    } while (0)

    ATT_PREF(0, 0);
    CP_COMMIT();
#pragma unroll
    for (int it = 0; it < 4; it++) {
        int idx = it * 256 + tid;
        int r = idx >> 3;
        int c8 = (idx & 7) * 8;
        int ig = qt * 128 + r;
        int4 val = make_int4(0, 0, 0, 0);
        if (ig < NT) val = *(const int4*)(qbase + (size_t)ig * DD + c8);
        *(int4*)(Qs + r * 72 + c8) = val;
    }
    __syncthreads();

    const int rowA = (lane & 7) + (((lane >> 3) & 1) << 3);
    const int colA = (lane >> 4) << 3;
    const int rowB = (lane & 7) + ((lane >> 4) << 3);
    const int colB = ((lane >> 3) & 1) << 3;

    uint32_t aq[4][4];
    {
        const int m0 = w * 16;
#pragma unroll
        for (int ks = 0; ks < 4; ks++) {
            uint32_t addr = smem_u32(Qs + (m0 + rowA) * 72 + ks * 16 + colA);
            LDSM4(aq[ks][0], aq[ks][1], aq[ks][2], aq[ks][3], addr);
        }
    }

    float o[8][4];
#pragma unroll
    for (int c = 0; c < 8; c++)
#pragma unroll
        for (int j = 0; j < 4; j++) o[c][j] = 0.0f;
    float lacc[4] = {0.0f, 0.0f, 0.0f, 0.0f};   // row-sum accumulator (ones-MMA)

    for (int kt = 0; kt < NKT; kt++) {
        const int cur = kt & 1;
        if (kt < NKT - 1) {
            ATT_PREF(kt + 1, 1 - cur);
            CP_COMMIT();
            CP_WAIT1();
        } else {
            CP_WAIT0();
        }
        __syncthreads();

        const __half* Ks = Ksb + cur * KVT;
        const __half* Vs = Vsb + cur * KVT;

        float s[8][4];
#pragma unroll
        for (int c = 0; c < 8; c++)
#pragma unroll
            for (int j = 0; j < 4; j++) s[c][j] = 0.0f;

#pragma unroll
        for (int ks = 0; ks < 4; ks++) {
#pragma unroll
            for (int np = 0; np < 4; np++) {
                uint32_t b0, b1, b2, b3;
                uint32_t addr = smem_u32(Ks + (np * 16 + rowB) * 72 + ks * 16 + colB);
                LDSM4(b0, b1, b2, b3, addr);
                mma_16816(s[np * 2],     aq[ks][0], aq[ks][1], aq[ks][2], aq[ks][3], b0, b1);
                mma_16816(s[np * 2 + 1], aq[ks][0], aq[ks][1], aq[ks][2], aq[ks][3], b2, b3);
            }
        }

        // p = 2^(s*T2 - M) in f16x2 (half the MUFU ops); tail tile masks c>0
        const bool lastk = (kt == LASTKT);
        uint32_t ph0[8], ph1[8];
#pragma unroll
        for (int c = 0; c < 8; c++) {
            float a0 = fmaf(s[c][0], T2, negM);
            float a1 = fmaf(s[c][1], T2, negM);
            float b0f = fmaf(s[c][2], T2, negM);
            float b1f = fmaf(s[c][3], T2, negM);
            uint32_t e0 = ex2_f16x2(cvt_f16x2(a0, a1));
            uint32_t e1 = ex2_f16x2(cvt_f16x2(b0f, b1f));
            if (lastk && c > 0) { e0 = 0u; e1 = 0u; }
            ph0[c] = e0;
            ph1[c] = e1;
        }

        // O += P @ V, and l via ones-MMA (exact row sums of the fp16 P)
#pragma unroll
        for (int ks = 0; ks < 4; ks++) {
            uint32_t a0 = ph0[2 * ks], a1 = ph1[2 * ks];
            uint32_t a2 = ph0[2 * ks + 1], a3 = ph1[2 * ks + 1];
            mma_16816(lacc, a0, a1, a2, a3, ONES16X2, ONES16X2);
#pragma unroll
            for (int np = 0; np < 4; np++) {
                uint32_t b0, b1, b2, b3;
                uint32_t addr = smem_u32(Vs + (ks * 16 + rowA) * 72 + np * 16 + colA);
                LDSM4T(b0, b1, b2, b3, addr);
                mma_16816(o[np * 2],     a0, a1, a2, a3, b0, b1);
                mma_16816(o[np * 2 + 1], a0, a1, a2, a3, b2, b3);
            }
        }
        __syncthreads();
    }
#undef ATT_PREF

    // Epilogue: lacc holds complete row sums (all n-cols identical).
    float inv0 = 1.0f / lacc[0];
    float inv1 = 1.0f / lacc[2];
    int t0 = qt * 128 + w * 16 + grp;
    if (t0 < NT) {
        __half* dst = g_oh + ((size_t)bh * NT + t0) * DD;
#pragma unroll
        for (int c = 0; c < 8; c++)
            *(__half2*)(dst + c * 8 + qd * 2) =
                __floats2half2_rn(o[c][0] * inv0, o[c][1] * inv0);
    }
    int t1 = t0 + 8;
    if (t1 < NT) {
        __half* dst = g_oh + ((size_t)bh * NT + t1) * DD;
#pragma unroll
        for (int c = 0; c < 8; c++)
            *(__half2*)(dst + c * 8 + qd * 2) =
                __floats2half2_rn(o[c][2] * inv1, o[c][3] * inv1);
    }
}

// ---------------------------------------------------------------------------
// Kernel 3: output projection (round-9 proven BK=32 version).
// ---------------------------------------------------------------------------
__global__ void __launch_bounds__(256, 2) out_mma_kernel(float* __restrict__ out)
{
    __shared__ __half Ah[2][128][40];
    __shared__ __half Bh[2][32][136];

    const int m0 = blockIdx.y * 128;
    const int n0 = blockIdx.x * 128;
    const int tid = threadIdx.x;
    const int w = tid >> 5;
    const int lane = tid & 31;
    const int grp = lane >> 2;
    const int qd = lane & 3;
    const int wm = w >> 1;
    const int wn = w & 1;

    const int rowA = (lane & 7) + (((lane >> 3) & 1) << 3);
    const int colA = (lane >> 4) << 3;

    const int ar = tid >> 1;
    const int ac = (tid & 1) * 16;
    const int am = m0 + ar;
    const int ab = am / NQ;
    const int at = am - ab * NQ;
    const int kr = tid >> 3;
    const int bc = (tid & 7) * 16;

#define OUT_PREF(kt, buf)                                                      \
    do {                                                                       \
        int k = (kt) * 32 + ac;                                                \
        int hh2 = k >> 6;                                                      \
        int dd2 = k & 63;                                                      \
        uint32_t ad = smem_u32(&Ah[buf][ar][ac]);                              \
        const __half* ag = g_oh + (((size_t)ab * HH + hh2) * NT + at) * DD + dd2; \
        CP_A16(ad, ag, true);                                                  \
        CP_A16(ad + 16, ag + 8, true);                                         \
        uint32_t bd = smem_u32(&Bh[buf][kr][bc]);                              \
        const __half* bg = g_wouth + (size_t)((kt) * 32 + kr) * CDIM + n0 + bc;\
        CP_A16(bd, bg, true);                                                  \
        CP_A16(bd + 16, bg + 8, true);                                         \
    } while (0)

    float acc[2][8][4];
#pragma unroll
    for (int i = 0; i < 2; i++)
#pragma unroll
        for (int j = 0; j < 8; j++)
#pragma unroll
            for (int r = 0; r < 4; r++) acc[i][j][r] = 0.0f;

    OUT_PREF(0, 0);
    CP_COMMIT();

    for (int kt = 0; kt < 16; kt++) {
        const int cur = kt & 1;
        if (kt < 15) {
            OUT_PREF(kt + 1, 1 - cur);
            CP_COMMIT();
            CP_WAIT1();
        } else {
            CP_WAIT0();
        }
        __syncthreads();
#pragma unroll
        for (int ks = 0; ks < 2; ks++) {
            uint32_t a[2][4];
#pragma unroll
            for (int mi = 0; mi < 2; mi++) {
                uint32_t addr = smem_u32(&Ah[cur][wm * 32 + mi * 16 + rowA][ks * 16 + colA]);
                LDSM4(a[mi][0], a[mi][1], a[mi][2], a[mi][3], addr);
            }
#pragma unroll
            for (int nc = 0; nc < 4; nc++) {
                uint32_t b0, b1, b2, b3;
                uint32_t addr = smem_u32(&Bh[cur][ks * 16 + rowA][wn * 64 + nc * 16 + colA]);
                LDSM4T(b0, b1, b2, b3, addr);
#pragma unroll
                for (int mi = 0; mi < 2; mi++) {
                    mma_16816(acc[mi][2 * nc],     a[mi][0], a[mi][1], a[mi][2], a[mi][3], b0, b1);
                    mma_16816(acc[mi][2 * nc + 1], a[mi][0], a[mi][1], a[mi][2], a[mi][3], b2, b3);
                }
            }
        }
        __syncthreads();
    }
#undef OUT_PREF

#pragma unroll
    for (int mi = 0; mi < 2; mi++) {
        int rbase = m0 + wm * 32 + mi * 16 + grp;
#pragma unroll
        for (int rr = 0; rr < 2; rr++) {
            int m = rbase + rr * 8;
            int b = m / NQ;
            int t = m - b * NQ;
            float* orow = out + ((size_t)b * NQ + t) * CDIM;
#pragma unroll
            for (int nc = 0; nc < 8; nc++) {
                int c = n0 + wn * 64 + nc * 8 + qd * 2;
                *(float2*)(orow + c) =
                    make_float2(acc[mi][nc][rr * 2], acc[mi][nc][rr * 2 + 1]);
            }
        }
    }
}

// ---------------------------------------------------------------------------
extern "C" void kernel_launch(void* const* d_in, const int* in_sizes, int n_in,
                              void* d_out, int out_size)
{
    const float* X    = (const float*)d_in[0];   // (4,2304,512)
    const float* S    = (const float*)d_in[1];   // (4,8,512)
    const float* Wqkv = (const float*)d_in[2];   // (512,1536)
    const float* Wout = (const float*)d_in[3];   // (512,512)
    const float* temp = (const float*)d_in[4];   // (8,1,1)
    float* out = (float*)d_out;                  // (4,2304,512)

    // 0. fp32 -> fp16 conversion
    {
        int blocks = (CVT_TOT + 255) / 256;
        convert_kernel<<<blocks, 256>>>(X, S, Wqkv, Wout);
    }
    // 1. QKV GEMM + fused l2norm epilogue
    {
        dim3 grid(1536 / 128, (M1 + 127) / 128);   // (12, 73)
        qkv_mma_kernel<<<grid, 256>>>();
    }
    // 2. Attention (f16x2 softmax, ones-MMA row sums)
    {
        size_t smem = (128 * 72 + 4 * KVT) * sizeof(__half);   // 55296 B
        (void)cudaFuncSetAttribute(attn_mma_kernel,
                                   cudaFuncAttributeMaxDynamicSharedMemorySize,
                                   (int)smem);
        dim3 grid(NQT, BB * HH);                   // (19, 32)
        attn_mma_kernel<<<grid, 256, smem>>>(temp);
    }
    // 3. Output projection
    {
        dim3 grid(CDIM / 128, M3 / 128);           // (4, 72)
        out_mma_kernel<<<grid, 256>>>(out);
    }
}

// round 15
// speedup vs baseline: 1.0377x; 1.0163x over previous
#include <cuda_runtime.h>
#include <cuda_fp16.h>
#include <cuda_bf16.h>
#include <math.h>
#include <stdint.h>

#define BB 4
#define NQ 2304
#define NT 2312           // NQ + 8 summary tokens
#define CDIM 512
#define HH 8
#define DD 64
#define M1 (BB * NT)      // 9248
#define M3 (BB * NQ)      // 9216
#define QKV_ELEMS (BB * HH * NT * DD)   // 4,734,976
#define NKT 37            // ceil(NT/64) key tiles
#define LASTKT 36
#define NQT 19            // ceil(NT/128) query tiles
#define KVT (64 * 72)     // one K or V buffer in halves
#define ONES16X2 0x3C003C00u   // half2(1.0, 1.0)

// GEMM 3-stage smem ring (halves): A stage 128x40, B stage 32x136
#define GSA 5120                       // one A stage in halves
#define GSB 4352                       // one B stage in halves
#define G_B_OFF (3 * GSA)              // B base offset in halves
#define G_SMEM_BYTES ((3 * GSA + 3 * GSB) * 2)   // 56832 B

// Scratch (no allocations allowed)
__device__ __half g_xh[M1 * CDIM];        // concat(X,S) fp16
__device__ __half g_wqkvh[CDIM * 1536];   // Wqkv fp16
__device__ __half g_wouth[CDIM * CDIM];   // Wout fp16
__device__ __half g_qh[QKV_ELEMS];        // normalized q fp16
__device__ __half g_kh[QKV_ELEMS];        // normalized k fp16
__device__ __half g_vh[QKV_ELEMS];        // v fp16
__device__ __half g_oh[QKV_ELEMS];        // attention output fp16

// ---------------------------------------------------------------------------
// helpers
// ---------------------------------------------------------------------------
static __device__ __forceinline__ uint32_t smem_u32(const void* p) {
    return (uint32_t)__cvta_generic_to_shared(p);
}

#define LDSM4(r0, r1, r2, r3, addr)                                            \
    asm volatile("ldmatrix.sync.aligned.m8n8.x4.shared.b16 {%0,%1,%2,%3}, [%4];" \
                 : "=r"(r0), "=r"(r1), "=r"(r2), "=r"(r3) : "r"(addr))

#define LDSM4T(r0, r1, r2, r3, addr)                                           \
    asm volatile("ldmatrix.sync.aligned.m8n8.x4.trans.shared.b16 {%0,%1,%2,%3}, [%4];" \
                 : "=r"(r0), "=r"(r1), "=r"(r2), "=r"(r3) : "r"(addr))

static __device__ __forceinline__ void mma_16816(
    float c[4], uint32_t a0, uint32_t a1, uint32_t a2, uint32_t a3,
    uint32_t b0, uint32_t b1)
{
    asm volatile(
        "mma.sync.aligned.m16n8k16.row.col.f32.f16.f16.f32 "
        "{%0,%1,%2,%3},{%4,%5,%6,%7},{%8,%9},{%0,%1,%2,%3};"
        : "+f"(c[0]), "+f"(c[1]), "+f"(c[2]), "+f"(c[3])
        : "r"(a0), "r"(a1), "r"(a2), "r"(a3), "r"(b0), "r"(b1));
}

// pack two fp32 into f16x2 (lo = x, hi = y)
static __device__ __forceinline__ uint32_t cvt_f16x2(float x, float y) {
    uint32_t r;
    asm("cvt.rn.f16x2.f32 %0, %1, %2;" : "=r"(r) : "f"(y), "f"(x));
    return r;
}
static __device__ __forceinline__ uint32_t ex2_f16x2(uint32_t a) {
    uint32_t r;
    asm("ex2.approx.f16x2 %0, %1;" : "=r"(r) : "r"(a));
    return r;
}

#define CP_A16(dst, src, valid)                                                \
    asm volatile("cp.async.ca.shared.global [%0], [%1], 16, %2;"               \
                 :: "r"(dst), "l"(src), "r"((valid) ? 16 : 0))
#define CP_COMMIT() asm volatile("cp.async.commit_group;")
#define CP_WAIT1()  asm volatile("cp.async.wait_group 1;")
#define CP_WAIT0()  asm volatile("cp.async.wait_group 0;")

// ---------------------------------------------------------------------------
// Kernel 0: fp32 -> fp16 conversion of inputs (concat X,S) and weights.
// ---------------------------------------------------------------------------
#define CVT_A   (M1 * CDIM / 4)             // 1183744
#define CVT_WQ  (CDIM * 1536 / 4)           // 196608
#define CVT_WO  (CDIM * CDIM / 4)           // 65536
#define CVT_TOT (CVT_A + CVT_WQ + CVT_WO)   // 1445888

__global__ void __launch_bounds__(256) convert_kernel(
    const float* __restrict__ X, const float* __restrict__ S,
    const float* __restrict__ Wq, const float* __restrict__ Wo)
{
    int i = blockIdx.x * 256 + threadIdx.x;
    if (i >= CVT_TOT) return;
    const float* src;
    __half* dst;
    if (i < CVT_A) {
        int row = i >> 7;
        int c4 = (i & 127) * 4;
        int b = row / NT;
        int t = row - b * NT;
        src = (t < NQ) ? X + ((size_t)b * NQ + t) * CDIM + c4
                       : S + ((size_t)b * 8 + (t - NQ)) * CDIM + c4;
        dst = g_xh + (size_t)row * CDIM + c4;
    } else if (i < CVT_A + CVT_WQ) {
        int j = (i - CVT_A) * 4;
        src = Wq + j;
        dst = g_wqkvh + j;
    } else {
        int j = (i - CVT_A - CVT_WQ) * 4;
        src = Wo + j;
        dst = g_wouth + j;
    }
    float4 v = *(const float4*)src;
    __half2 h0 = __floats2half2_rn(v.x, v.y);
    __half2 h1 = __floats2half2_rn(v.z, v.w);
    uint2 u;
    u.x = reinterpret_cast<uint32_t&>(h0);
    u.y = reinterpret_cast<uint32_t&>(h1);
    *(uint2*)dst = u;
}

// ---------------------------------------------------------------------------
// Kernel 1: QKV GEMM, BK=32, 3-stage cp.async ring, ONE barrier per chunk.
// Epilogue: fused L2-norm for q,k -> g_qh/g_kh; v -> g_vh.
// ---------------------------------------------------------------------------
__global__ void __launch_bounds__(256, 2) qkv_mma_kernel()
{
    extern __shared__ __half gsm[];
    __half* Ah = gsm;                 // 3 stages of [128][40]
    __half* Bh = gsm + G_B_OFF;       // 3 stages of [32][136]

    const int m0 = blockIdx.y * 128;
    const int n0 = blockIdx.x * 128;
    const int tid = threadIdx.x;
    const int w = tid >> 5;
    const int lane = tid & 31;
    const int grp = lane >> 2;
    const int qd = lane & 3;
    const int wm = w >> 1;
    const int wn = w & 1;

    const int rowA = (lane & 7) + (((lane >> 3) & 1) << 3);
    const int colA = (lane >> 4) << 3;

    const int ar = tid >> 1;
    const int ac = (tid & 1) * 16;
    const bool aok = (m0 + ar) < M1;
    const int kr = tid >> 3;
    const int bc = (tid & 7) * 16;

#define QKV_PREF(kt, st)                                                       \
    do {                                                                       \
        uint32_t ad = smem_u32(Ah + (st) * GSA + ar * 40 + ac);                \
        const __half* ag = g_xh + (size_t)(m0 + ar) * CDIM + (kt) * 32 + ac;   \
        CP_A16(ad, ag, aok);                                                   \
        CP_A16(ad + 16, ag + 8, aok);                                          \
        uint32_t bd = smem_u32(Bh + (st) * GSB + kr * 136 + bc);               \
        const __half* bg = g_wqkvh + (size_t)((kt) * 32 + kr) * 1536 + n0 + bc;\
        CP_A16(bd, bg, true);                                                  \
        CP_A16(bd + 16, bg + 8, true);                                         \
    } while (0)

    float acc[2][8][4];
#pragma unroll
    for (int i = 0; i < 2; i++)
#pragma unroll
        for (int j = 0; j < 8; j++)
#pragma unroll
            for (int r = 0; r < 4; r++) acc[i][j][r] = 0.0f;

    QKV_PREF(0, 0); CP_COMMIT();
    QKV_PREF(1, 1); CP_COMMIT();

    int sc = 0;        // compute stage
    int sp = 2;        // stage for chunk kt+2
    for (int kt = 0; kt < 16; kt++) {
        if (kt == 15) { CP_WAIT0(); } else { CP_WAIT1(); }
        __syncthreads();   // stage kt ready for all; all warps done with stage sp's old data
        if (kt < 14) {
            QKV_PREF(kt + 2, sp);
            CP_COMMIT();
            sp = (sp == 2) ? 0 : sp + 1;
        }
        const __half* Ac = Ah + sc * GSA;
        const __half* Bc = Bh + sc * GSB;
#pragma unroll
        for (int ks = 0; ks < 2; ks++) {
            uint32_t a[2][4];
#pragma unroll
            for (int mi = 0; mi < 2; mi++) {
                uint32_t addr = smem_u32(Ac + (wm * 32 + mi * 16 + rowA) * 40 + ks * 16 + colA);
                LDSM4(a[mi][0], a[mi][1], a[mi][2], a[mi][3], addr);
            }
#pragma unroll
            for (int nc = 0; nc < 4; nc++) {
                uint32_t b0, b1, b2, b3;
                uint32_t addr = smem_u32(Bc + (ks * 16 + rowA) * 136 + wn * 64 + nc * 16 + colA);
                LDSM4T(b0, b1, b2, b3, addr);
#pragma unroll
                for (int mi = 0; mi < 2; mi++) {
                    mma_16816(acc[mi][2 * nc],     a[mi][0], a[mi][1], a[mi][2], a[mi][3], b0, b1);
                    mma_16816(acc[mi][2 * nc + 1], a[mi][0], a[mi][1], a[mi][2], a[mi][3], b2, b3);
                }
            }
        }
        sc = (sc == 2) ? 0 : sc + 1;
    }
#undef QKV_PREF

    const int cbase = n0 + wn * 64;
    const int which = cbase >> 9;
    const int h = (cbase >> 6) & 7;
    __half* dstbase = (which == 0) ? g_qh : (which == 1) ? g_kh : g_vh;

#pragma unroll
    for (int mi = 0; mi < 2; mi++) {
#pragma unroll
        for (int rr = 0; rr < 2; rr++) {
            int m = m0 + wm * 32 + mi * 16 + rr * 8 + grp;
            float inv = 1.0f;
            if (which < 2) {
                float ss = 0.0f;
#pragma unroll
                for (int nc = 0; nc < 8; nc++) {
                    float a0 = acc[mi][nc][rr * 2];
                    float a1 = acc[mi][nc][rr * 2 + 1];
                    ss += a0 * a0 + a1 * a1;
                }
                ss += __shfl_xor_sync(0xffffffffu, ss, 1);
                ss += __shfl_xor_sync(0xffffffffu, ss, 2);
                inv = 1.0f / fmaxf(sqrtf(ss), 1e-12f);
            }
            if (m < M1) {
                int b = m / NT;
                int t = m - b * NT;
                __half* dst = dstbase + (((size_t)b * HH + h) * NT + t) * DD;
#pragma unroll
                for (int nc = 0; nc < 8; nc++) {
                    *(__half2*)(dst + nc * 8 + qd * 2) = __floats2half2_rn(
                        acc[mi][nc][rr * 2] * inv, acc[mi][nc][rr * 2 + 1] * inv);
                }
            }
        }
    }
}

// ---------------------------------------------------------------------------
// Kernel 2: Flash attention (round-14: f16x2 ex2 + ones-MMA row sums).
// ---------------------------------------------------------------------------
__global__ void __launch_bounds__(256, 2) attn_mma_kernel(const float* __restrict__ temp)
{
    extern __shared__ __half dynsm[];
    __half* Qs  = dynsm;                   // 128*72
    __half* Ksb = dynsm + 128 * 72;        // 2 * KVT
    __half* Vsb = Ksb + 2 * KVT;           // 2 * KVT

    const int bh = blockIdx.y;
    const int h = bh & (HH - 1);
    const int qt = blockIdx.x;
    const int tid = threadIdx.x;
    const int w = tid >> 5;
    const int lane = tid & 31;
    const int grp = lane >> 2;
    const int qd = lane & 3;
    const float T2 = temp[h] * 1.44269504089f;
    const float negM = -fabsf(T2) - 0.01f;

    const __half* qbase = g_qh + (size_t)bh * NT * DD;
    const __half* kbase = g_kh + (size_t)bh * NT * DD;
    const __half* vbase = g_vh + (size_t)bh * NT * DD;

    const int r_ = tid >> 2;           // 0..63
    const int cc_ = (tid & 3) * 16;    // 0,16,32,48

#define ATT_PREF(kt, buf)                                                      \
    do {                                                                       \
        int jg = (kt) * 64 + r_;                                               \
        bool v = jg < NT;                                                      \
        const __half* kg = kbase + (size_t)jg * DD + cc_;                      \
        const __half* vg = vbase + (size_t)jg * DD + cc_;                      \
        uint32_t kd = smem_u32(Ksb + (buf) * KVT + r_ * 72 + cc_);             \
        uint32_t vd = smem_u32(Vsb + (buf) * KVT + r_ * 72 + cc_);             \
        CP_A16(kd, kg, v); CP_A16(kd + 16, kg + 8, v);                         \
        CP_A16(vd, vg, v); CP_A16(vd + 16, vg + 8, v);                         \
    } while (0)

    ATT_PREF(0, 0);
    CP_COMMIT();
#pragma unroll
    for (int it = 0; it < 4; it++) {
        int idx = it * 256 + tid;
        int r = idx >> 3;
        int c8 = (idx & 7) * 8;
        int ig = qt * 128 + r;
        int4 val = make_int4(0, 0, 0, 0);
        if (ig < NT) val = *(const int4*)(qbase + (size_t)ig * DD + c8);
        *(int4*)(Qs + r * 72 + c8) = val;
    }
    __syncthreads();

    const int rowA = (lane & 7) + (((lane >> 3) & 1) << 3);
    const int colA = (lane >> 4) << 3;
    const int rowB = (lane & 7) + ((lane >> 4) << 3);
    const int colB = ((lane >> 3) & 1) << 3;

    uint32_t aq[4][4];
    {
        const int m0 = w * 16;
#pragma unroll
        for (int ks = 0; ks < 4; ks++) {
            uint32_t addr = smem_u32(Qs + (m0 + rowA) * 72 + ks * 16 + colA);
            LDSM4(aq[ks][0], aq[ks][1], aq[ks][2], aq[ks][3], addr);
        }
    }

    float o[8][4];
#pragma unroll
    for (int c = 0; c < 8; c++)
#pragma unroll
        for (int j = 0; j < 4; j++) o[c][j] = 0.0f;
    float lacc[4] = {0.0f, 0.0f, 0.0f, 0.0f};

    for (int kt = 0; kt < NKT; kt++) {
        const int cur = kt & 1;
        if (kt < NKT - 1) {
            ATT_PREF(kt + 1, 1 - cur);
            CP_COMMIT();
            CP_WAIT1();
        } else {
            CP_WAIT0();
        }
        __syncthreads();

        const __half* Ks = Ksb + cur * KVT;
        const __half* Vs = Vsb + cur * KVT;

        float s[8][4];
#pragma unroll
        for (int c = 0; c < 8; c++)
#pragma unroll
            for (int j = 0; j < 4; j++) s[c][j] = 0.0f;

#pragma unroll
        for (int ks = 0; ks < 4; ks++) {
#pragma unroll
            for (int np = 0; np < 4; np++) {
                uint32_t b0, b1, b2, b3;
                uint32_t addr = smem_u32(Ks + (np * 16 + rowB) * 72 + ks * 16 + colB);
                LDSM4(b0, b1, b2, b3, addr);
                mma_16816(s[np * 2],     aq[ks][0], aq[ks][1], aq[ks][2], aq[ks][3], b0, b1);
                mma_16816(s[np * 2 + 1], aq[ks][0], aq[ks][1], aq[ks][2], aq[ks][3], b2, b3);
            }
        }

        const bool lastk = (kt == LASTKT);
        uint32_t ph0[8], ph1[8];
#pragma unroll
        for (int c = 0; c < 8; c++) {
            float a0 = fmaf(s[c][0], T2, negM);
            float a1 = fmaf(s[c][1], T2, negM);
            float b0f = fmaf(s[c][2], T2, negM);
            float b1f = fmaf(s[c][3], T2, negM);
            uint32_t e0 = ex2_f16x2(cvt_f16x2(a0, a1));
            uint32_t e1 = ex2_f16x2(cvt_f16x2(b0f, b1f));
            if (lastk && c > 0) { e0 = 0u; e1 = 0u; }
            ph0[c] = e0;
            ph1[c] = e1;
        }

#pragma unroll
        for (int ks = 0; ks < 4; ks++) {
            uint32_t a0 = ph0[2 * ks], a1 = ph1[2 * ks];
            uint32_t a2 = ph0[2 * ks + 1], a3 = ph1[2 * ks + 1];
            mma_16816(lacc, a0, a1, a2, a3, ONES16X2, ONES16X2);
#pragma unroll
            for (int np = 0; np < 4; np++) {
                uint32_t b0, b1, b2, b3;
                uint32_t addr = smem_u32(Vs + (ks * 16 + rowA) * 72 + np * 16 + colA);
                LDSM4T(b0, b1, b2, b3, addr);
                mma_16816(o[np * 2],     a0, a1, a2, a3, b0, b1);
                mma_16816(o[np * 2 + 1], a0, a1, a2, a3, b2, b3);
            }
        }
        __syncthreads();
    }
#undef ATT_PREF

    float inv0 = 1.0f / lacc[0];
    float inv1 = 1.0f / lacc[2];
    int t0 = qt * 128 + w * 16 + grp;
    if (t0 < NT) {
        __half* dst = g_oh + ((size_t)bh * NT + t0) * DD;
#pragma unroll
        for (int c = 0; c < 8; c++)
            *(__half2*)(dst + c * 8 + qd * 2) =
                __floats2half2_rn(o[c][0] * inv0, o[c][1] * inv0);
    }
    int t1 = t0 + 8;
    if (t1 < NT) {
        __half* dst = g_oh + ((size_t)bh * NT + t1) * DD;
#pragma unroll
        for (int c = 0; c < 8; c++)
            *(__half2*)(dst + c * 8 + qd * 2) =
                __floats2half2_rn(o[c][2] * inv1, o[c][3] * inv1);
    }
}

// ---------------------------------------------------------------------------
// Kernel 3: output projection, BK=32, 3-stage ring, one barrier per chunk.
// ---------------------------------------------------------------------------
__global__ void __launch_bounds__(256, 2) out_mma_kernel(float* __restrict__ out)
{
    extern __shared__ __half gsm[];
    __half* Ah = gsm;
    __half* Bh = gsm + G_B_OFF;

    const int m0 = blockIdx.y * 128;
    const int n0 = blockIdx.x * 128;
    const int tid = threadIdx.x;
    const int w = tid >> 5;
    const int lane = tid & 31;
    const int grp = lane >> 2;
    const int qd = lane & 3;
    const int wm = w >> 1;
    const int wn = w & 1;

    const int rowA = (lane & 7) + (((lane >> 3) & 1) << 3);
    const int colA = (lane >> 4) << 3;

    const int ar = tid >> 1;
    const int ac = (tid & 1) * 16;
    const int am = m0 + ar;
    const int ab = am / NQ;
    const int at = am - ab * NQ;
    const int kr = tid >> 3;
    const int bc = (tid & 7) * 16;

#define OUT_PREF(kt, st)                                                       \
    do {                                                                       \
        int k = (kt) * 32 + ac;                                                \
        int hh2 = k >> 6;                                                      \
        int dd2 = k & 63;                                                      \
        uint32_t ad = smem_u32(Ah + (st) * GSA + ar * 40 + ac);                \
        const __half* ag = g_oh + (((size_t)ab * HH + hh2) * NT + at) * DD + dd2; \
        CP_A16(ad, ag, true);                                                  \
        CP_A16(ad + 16, ag + 8, true);                                         \
        uint32_t bd = smem_u32(Bh + (st) * GSB + kr * 136 + bc);               \
        const __half* bg = g_wouth + (size_t)((kt) * 32 + kr) * CDIM + n0 + bc;\
        CP_A16(bd, bg, true);                                                  \
        CP_A16(bd + 16, bg + 8, true);                                         \
    } while (0)

    float acc[2][8][4];
#pragma unroll
    for (int i = 0; i < 2; i++)
#pragma unroll
        for (int j = 0; j < 8; j++)
#pragma unroll
            for (int r = 0; r < 4; r++) acc[i][j][r] = 0.0f;

    OUT_PREF(0, 0); CP_COMMIT();
    OUT_PREF(1, 1); CP_COMMIT();

    int sc = 0;
    int sp = 2;
    for (int kt = 0; kt < 16; kt++) {
        if (kt == 15) { CP_WAIT0(); } else { CP_WAIT1(); }
        __syncthreads();
        if (kt < 14) {
            OUT_PREF(kt + 2, sp);
            CP_COMMIT();
            sp = (sp == 2) ? 0 : sp + 1;
        }
        const __half* Ac = Ah + sc * GSA;
        const __half* Bc = Bh + sc * GSB;
#pragma unroll
        for (int ks = 0; ks < 2; ks++) {
            uint32_t a[2][4];
#pragma unroll
            for (int mi = 0; mi < 2; mi++) {
                uint32_t addr = smem_u32(Ac + (wm * 32 + mi * 16 + rowA) * 40 + ks * 16 + colA);
                LDSM4(a[mi][0], a[mi][1], a[mi][2], a[mi][3], addr);
            }
#pragma unroll
            for (int nc = 0; nc < 4; nc++) {
                uint32_t b0, b1, b2, b3;
                uint32_t addr = smem_u32(Bc + (ks * 16 + rowA) * 136 + wn * 64 + nc * 16 + colA);
                LDSM4T(b0, b1, b2, b3, addr);
#pragma unroll
                for (int mi = 0; mi < 2; mi++) {
                    mma_16816(acc[mi][2 * nc],     a[mi][0], a[mi][1], a[mi][2], a[mi][3], b0, b1);
                    mma_16816(acc[mi][2 * nc + 1], a[mi][0], a[mi][1], a[mi][2], a[mi][3], b2, b3);
                }
            }
        }
        sc = (sc == 2) ? 0 : sc + 1;
    }
#undef OUT_PREF

#pragma unroll
    for (int mi = 0; mi < 2; mi++) {
        int rbase = m0 + wm * 32 + mi * 16 + grp;
#pragma unroll
        for (int rr = 0; rr < 2; rr++) {
            int m = rbase + rr * 8;
            int b = m / NQ;
            int t = m - b * NQ;
            float* orow = out + ((size_t)b * NQ + t) * CDIM;
#pragma unroll
            for (int nc = 0; nc < 8; nc++) {
                int c = n0 + wn * 64 + nc * 8 + qd * 2;
                *(float2*)(orow + c) =
                    make_float2(acc[mi][nc][rr * 2], acc[mi][nc][rr * 2 + 1]);
            }
        }
    }
}

// ---------------------------------------------------------------------------
extern "C" void kernel_launch(void* const* d_in, const int* in_sizes, int n_in,
                              void* d_out, int out_size)
{
    const float* X    = (const float*)d_in[0];   // (4,2304,512)
    const float* S    = (const float*)d_in[1];   // (4,8,512)
    const float* Wqkv = (const float*)d_in[2];   // (512,1536)
    const float* Wout = (const float*)d_in[3];   // (512,512)
    const float* temp = (const float*)d_in[4];   // (8,1,1)
    float* out = (float*)d_out;                  // (4,2304,512)

    // 0. fp32 -> fp16 conversion
    {
        int blocks = (CVT_TOT + 255) / 256;
        convert_kernel<<<blocks, 256>>>(X, S, Wqkv, Wout);
    }
    // 1. QKV GEMM + fused l2norm epilogue (3-stage ring)
    {
        (void)cudaFuncSetAttribute(qkv_mma_kernel,
                                   cudaFuncAttributeMaxDynamicSharedMemorySize,
                                   G_SMEM_BYTES);
        dim3 grid(1536 / 128, (M1 + 127) / 128);   // (12, 73)
        qkv_mma_kernel<<<grid, 256, G_SMEM_BYTES>>>();
    }
    // 2. Attention (f16x2 softmax, ones-MMA row sums)
    {
        size_t smem = (128 * 72 + 4 * KVT) * sizeof(__half);   // 55296 B
        (void)cudaFuncSetAttribute(attn_mma_kernel,
                                   cudaFuncAttributeMaxDynamicSharedMemorySize,
                                   (int)smem);
        dim3 grid(NQT, BB * HH);                   // (19, 32)
        attn_mma_kernel<<<grid, 256, smem>>>(temp);
    }
    // 3. Output projection (3-stage ring)
    {
        (void)cudaFuncSetAttribute(out_mma_kernel,
                                   cudaFuncAttributeMaxDynamicSharedMemorySize,
                                   G_SMEM_BYTES);
        dim3 grid(CDIM / 128, M3 / 128);           // (4, 72)
        out_mma_kernel<<<grid, 256, G_SMEM_BYTES>>>(out);
    }
}

// round 17
// speedup vs baseline: 1.0543x; 1.0160x over previous
#include <cuda_runtime.h>
#include <cuda_fp16.h>
#include <cuda_bf16.h>
#include <math.h>
#include <stdint.h>

#define BB 4
#define NQ 2304
#define NT 2312           // NQ + 8 summary tokens
#define CDIM 512
#define HH 8
#define DD 64
#define M1 (BB * NT)      // 9248
#define M3 (BB * NQ)      // 9216
#define QKV_ELEMS (BB * HH * NT * DD)   // 4,734,976
#define NKT 37            // ceil(NT/64) key tiles
#define LASTKT 36
#define NQT 19            // ceil(NT/128) query tiles
#define NTILES (NQT * BB * HH)   // 608 attention tiles
#define NCTA_ATT 592             // 2 * 296 concurrency; 16 CTAs take 2 tiles
#define KVT (64 * 72)     // one K or V buffer in halves
#define ONES16X2 0x3C003C00u   // half2(1.0, 1.0)

// GEMM 3-stage smem ring (halves): A stage 128x40, B stage 32x136
#define GSA 5120
#define GSB 4352
#define G_B_OFF (3 * GSA)
#define G_SMEM_BYTES ((3 * GSA + 3 * GSB) * 2)   // 56832 B

// Scratch (no allocations allowed)
__device__ __half g_xh[M1 * CDIM];        // concat(X,S) fp16
__device__ __half g_wqkvh[CDIM * 1536];   // Wqkv fp16
__device__ __half g_wouth[CDIM * CDIM];   // Wout fp16
__device__ __half g_qh[QKV_ELEMS];        // normalized q fp16
__device__ __half g_kh[QKV_ELEMS];        // normalized k fp16
__device__ __half g_vh[QKV_ELEMS];        // v fp16
__device__ __half g_oh[QKV_ELEMS];        // attention output fp16

// ---------------------------------------------------------------------------
// helpers
// ---------------------------------------------------------------------------
static __device__ __forceinline__ uint32_t smem_u32(const void* p) {
    return (uint32_t)__cvta_generic_to_shared(p);
}

#define LDSM4(r0, r1, r2, r3, addr)                                            \
    asm volatile("ldmatrix.sync.aligned.m8n8.x4.shared.b16 {%0,%1,%2,%3}, [%4];" \
                 : "=r"(r0), "=r"(r1), "=r"(r2), "=r"(r3) : "r"(addr))

#define LDSM4T(r0, r1, r2, r3, addr)                                           \
    asm volatile("ldmatrix.sync.aligned.m8n8.x4.trans.shared.b16 {%0,%1,%2,%3}, [%4];" \
                 : "=r"(r0), "=r"(r1), "=r"(r2), "=r"(r3) : "r"(addr))

static __device__ __forceinline__ void mma_16816(
    float c[4], uint32_t a0, uint32_t a1, uint32_t a2, uint32_t a3,
    uint32_t b0, uint32_t b1)
{
    asm volatile(
        "mma.sync.aligned.m16n8k16.row.col.f32.f16.f16.f32 "
        "{%0,%1,%2,%3},{%4,%5,%6,%7},{%8,%9},{%0,%1,%2,%3};"
        : "+f"(c[0]), "+f"(c[1]), "+f"(c[2]), "+f"(c[3])
        : "r"(a0), "r"(a1), "r"(a2), "r"(a3), "r"(b0), "r"(b1));
}

static __device__ __forceinline__ uint32_t cvt_f16x2(float x, float y) {
    uint32_t r;
    asm("cvt.rn.f16x2.f32 %0, %1, %2;" : "=r"(r) : "f"(y), "f"(x));
    return r;
}
static __device__ __forceinline__ uint32_t ex2_f16x2(uint32_t a) {
    uint32_t r;
    asm("ex2.approx.f16x2 %0, %1;" : "=r"(r) : "r"(a));
    return r;
}

#define CP_A16(dst, src, valid)                                                \
    asm volatile("cp.async.ca.shared.global [%0], [%1], 16, %2;"               \
                 :: "r"(dst), "l"(src), "r"((valid) ? 16 : 0))
#define CP_COMMIT() asm volatile("cp.async.commit_group;")
#define CP_WAIT1()  asm volatile("cp.async.wait_group 1;")
#define CP_WAIT0()  asm volatile("cp.async.wait_group 0;")

// ---------------------------------------------------------------------------
// Kernel 0: fp32 -> fp16 conversion of inputs (concat X,S) and weights.
// ---------------------------------------------------------------------------
#define CVT_A   (M1 * CDIM / 4)
#define CVT_WQ  (CDIM * 1536 / 4)
#define CVT_WO  (CDIM * CDIM / 4)
#define CVT_TOT (CVT_A + CVT_WQ + CVT_WO)

__global__ void __launch_bounds__(256) convert_kernel(
    const float* __restrict__ X, const float* __restrict__ S,
    const float* __restrict__ Wq, const float* __restrict__ Wo)
{
    int i = blockIdx.x * 256 + threadIdx.x;
    if (i >= CVT_TOT) return;
    const float* src;
    __half* dst;
    if (i < CVT_A) {
        int row = i >> 7;
        int c4 = (i & 127) * 4;
        int b = row / NT;
        int t = row - b * NT;
        src = (t < NQ) ? X + ((size_t)b * NQ + t) * CDIM + c4
                       : S + ((size_t)b * 8 + (t - NQ)) * CDIM + c4;
        dst = g_xh + (size_t)row * CDIM + c4;
    } else if (i < CVT_A + CVT_WQ) {
        int j = (i - CVT_A) * 4;
        src = Wq + j;
        dst = g_wqkvh + j;
    } else {
        int j = (i - CVT_A - CVT_WQ) * 4;
        src = Wo + j;
        dst = g_wouth + j;
    }
    float4 v = *(const float4*)src;
    __half2 h0 = __floats2half2_rn(v.x, v.y);
    __half2 h1 = __floats2half2_rn(v.z, v.w);
    uint2 u;
    u.x = reinterpret_cast<uint32_t&>(h0);
    u.y = reinterpret_cast<uint32_t&>(h1);
    *(uint2*)dst = u;
}

// ---------------------------------------------------------------------------
// Kernel 1: QKV GEMM, BK=32, 3-stage cp.async ring (round-15 proven).
// Epilogue: fused L2-norm for q,k -> g_qh/g_kh; v -> g_vh.
// ---------------------------------------------------------------------------
__global__ void __launch_bounds__(256, 2) qkv_mma_kernel()
{
    extern __shared__ __half gsm[];
    __half* Ah = gsm;
    __half* Bh = gsm + G_B_OFF;

    const int m0 = blockIdx.y * 128;
    const int n0 = blockIdx.x * 128;
    const int tid = threadIdx.x;
    const int w = tid >> 5;
    const int lane = tid & 31;
    const int grp = lane >> 2;
    const int qd = lane & 3;
    const int wm = w >> 1;
    const int wn = w & 1;

    const int rowA = (lane & 7) + (((lane >> 3) & 1) << 3);
    const int colA = (lane >> 4) << 3;

    const int ar = tid >> 1;
    const int ac = (tid & 1) * 16;
    const bool aok = (m0 + ar) < M1;
    const int kr = tid >> 3;
    const int bc = (tid & 7) * 16;

#define QKV_PREF(kt, st)                                                       \
    do {                                                                       \
        uint32_t ad = smem_u32(Ah + (st) * GSA + ar * 40 + ac);                \
        const __half* ag = g_xh + (size_t)(m0 + ar) * CDIM + (kt) * 32 + ac;   \
        CP_A16(ad, ag, aok);                                                   \
        CP_A16(ad + 16, ag + 8, aok);                                          \
        uint32_t bd = smem_u32(Bh + (st) * GSB + kr * 136 + bc);               \
        const __half* bg = g_wqkvh + (size_t)((kt) * 32 + kr) * 1536 + n0 + bc;\
        CP_A16(bd, bg, true);                                                  \
        CP_A16(bd + 16, bg + 8, true);                                         \
    } while (0)

    float acc[2][8][4];
#pragma unroll
    for (int i = 0; i < 2; i++)
#pragma unroll
        for (int j = 0; j < 8; j++)
#pragma unroll
            for (int r = 0; r < 4; r++) acc[i][j][r] = 0.0f;

    QKV_PREF(0, 0); CP_COMMIT();
    QKV_PREF(1, 1); CP_COMMIT();

    int sc = 0;
    int sp = 2;
    for (int kt = 0; kt < 16; kt++) {
        if (kt == 15) { CP_WAIT0(); } else { CP_WAIT1(); }
        __syncthreads();
        if (kt < 14) {
            QKV_PREF(kt + 2, sp);
            CP_COMMIT();
            sp = (sp == 2) ? 0 : sp + 1;
        }
        const __half* Ac = Ah + sc * GSA;
        const __half* Bc = Bh + sc * GSB;
#pragma unroll
        for (int ks = 0; ks < 2; ks++) {
            uint32_t a[2][4];
#pragma unroll
            for (int mi = 0; mi < 2; mi++) {
                uint32_t addr = smem_u32(Ac + (wm * 32 + mi * 16 + rowA) * 40 + ks * 16 + colA);
                LDSM4(a[mi][0], a[mi][1], a[mi][2], a[mi][3], addr);
            }
#pragma unroll
            for (int nc = 0; nc < 4; nc++) {
                uint32_t b0, b1, b2, b3;
                uint32_t addr = smem_u32(Bc + (ks * 16 + rowA) * 136 + wn * 64 + nc * 16 + colA);
                LDSM4T(b0, b1, b2, b3, addr);
#pragma unroll
                for (int mi = 0; mi < 2; mi++) {
                    mma_16816(acc[mi][2 * nc],     a[mi][0], a[mi][1], a[mi][2], a[mi][3], b0, b1);
                    mma_16816(acc[mi][2 * nc + 1], a[mi][0], a[mi][1], a[mi][2], a[mi][3], b2, b3);
                }
            }
        }
        sc = (sc == 2) ? 0 : sc + 1;
    }
#undef QKV_PREF

    const int cbase = n0 + wn * 64;
    const int which = cbase >> 9;
    const int h = (cbase >> 6) & 7;
    __half* dstbase = (which == 0) ? g_qh : (which == 1) ? g_kh : g_vh;

#pragma unroll
    for (int mi = 0; mi < 2; mi++) {
#pragma unroll
        for (int rr = 0; rr < 2; rr++) {
            int m = m0 + wm * 32 + mi * 16 + rr * 8 + grp;
            float inv = 1.0f;
            if (which < 2) {
                float ss = 0.0f;
#pragma unroll
                for (int nc = 0; nc < 8; nc++) {
                    float a0 = acc[mi][nc][rr * 2];
                    float a1 = acc[mi][nc][rr * 2 + 1];
                    ss += a0 * a0 + a1 * a1;
                }
                ss += __shfl_xor_sync(0xffffffffu, ss, 1);
                ss += __shfl_xor_sync(0xffffffffu, ss, 2);
                inv = 1.0f / fmaxf(sqrtf(ss), 1e-12f);
            }
            if (m < M1) {
                int b = m / NT;
                int t = m - b * NT;
                __half* dst = dstbase + (((size_t)b * HH + h) * NT + t) * DD;
#pragma unroll
                for (int nc = 0; nc < 8; nc++) {
                    *(__half2*)(dst + nc * 8 + qd * 2) = __floats2half2_rn(
                        acc[mi][nc][rr * 2] * inv, acc[mi][nc][rr * 2 + 1] * inv);
                }
            }
        }
    }
}

// ---------------------------------------------------------------------------
// Kernel 2: Flash attention, wave-balanced 1D grid of 592 CTAs.
// CTAs 0..15 process 2 tiles (flat ids 2c, 2c+1); CTAs 16..591 process
// tile id cid+16. 608 tiles total; makespan = 2 waves instead of 3.
// Per-tile body identical to round-14/15 (f16x2 ex2 + ones-MMA row sums).
// ---------------------------------------------------------------------------
__global__ void __launch_bounds__(256, 2) attn_mma_kernel(const float* __restrict__ temp)
{
    extern __shared__ __half dynsm[];
    __half* Qs  = dynsm;                   // 128*72
    __half* Ksb = dynsm + 128 * 72;        // 2 * KVT
    __half* Vsb = Ksb + 2 * KVT;           // 2 * KVT

    const int tid = threadIdx.x;
    const int w = tid >> 5;
    const int lane = tid & 31;
    const int grp = lane >> 2;
    const int qd = lane & 3;

    const int rowA = (lane & 7) + (((lane >> 3) & 1) << 3);
    const int colA = (lane >> 4) << 3;
    const int rowB = (lane & 7) + ((lane >> 4) << 3);
    const int colB = ((lane >> 3) & 1) << 3;

    const int r_ = tid >> 2;           // 0..63
    const int cc_ = (tid & 3) * 16;    // 0,16,32,48

    const int cid = blockIdx.x;
    int tstart, nrep;
    if (cid < 16) { tstart = 2 * cid; nrep = 2; }
    else          { tstart = cid + 16; nrep = 1; }

    for (int rep = 0; rep < nrep; rep++) {
        const int tt = tstart + rep;
        const int bh = tt / NQT;
        const int qt = tt - bh * NQT;
        const int h = bh & (HH - 1);
        const float T2 = temp[h] * 1.44269504089f;
        const float negM = -fabsf(T2) - 0.01f;

        const __half* qbase = g_qh + (size_t)bh * NT * DD;
        const __half* kbase = g_kh + (size_t)bh * NT * DD;
        const __half* vbase = g_vh + (size_t)bh * NT * DD;

#define ATT_PREF(kt, buf)                                                      \
    do {                                                                       \
        int jg = (kt) * 64 + r_;                                               \
        bool v = jg < NT;                                                      \
        const __half* kg = kbase + (size_t)jg * DD + cc_;                      \
        const __half* vg = vbase + (size_t)jg * DD + cc_;                      \
        uint32_t kd = smem_u32(Ksb + (buf) * KVT + r_ * 72 + cc_);             \
        uint32_t vd = smem_u32(Vsb + (buf) * KVT + r_ * 72 + cc_);             \
        CP_A16(kd, kg, v); CP_A16(kd + 16, kg + 8, v);                         \
        CP_A16(vd, vg, v); CP_A16(vd + 16, vg + 8, v);                         \
    } while (0)

        if (rep > 0) __syncthreads();   // prior tile fully done with smem
        ATT_PREF(0, 0);
        CP_COMMIT();
#pragma unroll
        for (int it = 0; it < 4; it++) {
            int idx = it * 256 + tid;
            int r = idx >> 3;
            int c8 = (idx & 7) * 8;
            int ig = qt * 128 + r;
            int4 val = make_int4(0, 0, 0, 0);
            if (ig < NT) val = *(const int4*)(qbase + (size_t)ig * DD + c8);
            *(int4*)(Qs + r * 72 + c8) = val;
        }
        __syncthreads();

        uint32_t aq[4][4];
        {
            const int m0 = w * 16;
#pragma unroll
            for (int ks = 0; ks < 4; ks++) {
                uint32_t addr = smem_u32(Qs + (m0 + rowA) * 72 + ks * 16 + colA);
                LDSM4(aq[ks][0], aq[ks][1], aq[ks][2], aq[ks][3], addr);
            }
        }

        float o[8][4];
#pragma unroll
        for (int c = 0; c < 8; c++)
#pragma unroll
            for (int j = 0; j < 4; j++) o[c][j] = 0.0f;
        float lacc[4] = {0.0f, 0.0f, 0.0f, 0.0f};

        for (int kt = 0; kt < NKT; kt++) {
            const int cur = kt & 1;
            if (kt < NKT - 1) {
                ATT_PREF(kt + 1, 1 - cur);
                CP_COMMIT();
                CP_WAIT1();
            } else {
                CP_WAIT0();
            }
            __syncthreads();

            const __half* Ks = Ksb + cur * KVT;
            const __half* Vs = Vsb + cur * KVT;

            float s[8][4];
#pragma unroll
            for (int c = 0; c < 8; c++)
#pragma unroll
                for (int j = 0; j < 4; j++) s[c][j] = 0.0f;

#pragma unroll
            for (int ks = 0; ks < 4; ks++) {
#pragma unroll
                for (int np = 0; np < 4; np++) {
                    uint32_t b0, b1, b2, b3;
                    uint32_t addr = smem_u32(Ks + (np * 16 + rowB) * 72 + ks * 16 + colB);
                    LDSM4(b0, b1, b2, b3, addr);
                    mma_16816(s[np * 2],     aq[ks][0], aq[ks][1], aq[ks][2], aq[ks][3], b0, b1);
                    mma_16816(s[np * 2 + 1], aq[ks][0], aq[ks][1], aq[ks][2], aq[ks][3], b2, b3);
                }
            }

            const bool lastk = (kt == LASTKT);
            uint32_t ph0[8], ph1[8];
#pragma unroll
            for (int c = 0; c < 8; c++) {
                float a0 = fmaf(s[c][0], T2, negM);
                float a1 = fmaf(s[c][1], T2, negM);
                float b0f = fmaf(s[c][2], T2, negM);
                float b1f = fmaf(s[c][3], T2, negM);
                uint32_t e0 = ex2_f16x2(cvt_f16x2(a0, a1));
                uint32_t e1 = ex2_f16x2(cvt_f16x2(b0f, b1f));
                if (lastk && c > 0) { e0 = 0u; e1 = 0u; }
                ph0[c] = e0;
                ph1[c] = e1;
            }

#pragma unroll
            for (int ks = 0; ks < 4; ks++) {
                uint32_t a0 = ph0[2 * ks], a1 = ph1[2 * ks];
                uint32_t a2 = ph0[2 * ks + 1], a3 = ph1[2 * ks + 1];
                mma_16816(lacc, a0, a1, a2, a3, ONES16X2, ONES16X2);
#pragma unroll
                for (int np = 0; np < 4; np++) {
                    uint32_t b0, b1, b2, b3;
                    uint32_t addr = smem_u32(Vs + (ks * 16 + rowA) * 72 + np * 16 + colA);
                    LDSM4T(b0, b1, b2, b3, addr);
                    mma_16816(o[np * 2],     a0, a1, a2, a3, b0, b1);
                    mma_16816(o[np * 2 + 1], a0, a1, a2, a3, b2, b3);
                }
            }
            __syncthreads();
        }
#undef ATT_PREF

        float inv0 = 1.0f / lacc[0];
        float inv1 = 1.0f / lacc[2];
        int t0 = qt * 128 + w * 16 + grp;
        if (t0 < NT) {
            __half* dst = g_oh + ((size_t)bh * NT + t0) * DD;
#pragma unroll
            for (int c = 0; c < 8; c++)
                *(__half2*)(dst + c * 8 + qd * 2) =
                    __floats2half2_rn(o[c][0] * inv0, o[c][1] * inv0);
        }
        int t1 = t0 + 8;
        if (t1 < NT) {
            __half* dst = g_oh + ((size_t)bh * NT + t1) * DD;
#pragma unroll
            for (int c = 0; c < 8; c++)
                *(__half2*)(dst + c * 8 + qd * 2) =
                    __floats2half2_rn(o[c][2] * inv1, o[c][3] * inv1);
        }
    }
}

// ---------------------------------------------------------------------------
// Kernel 3: output projection, BK=32, 3-stage ring (round-15 proven).
// ---------------------------------------------------------------------------
__global__ void __launch_bounds__(256, 2) out_mma_kernel(float* __restrict__ out)
{
    extern __shared__ __half gsm[];
    __half* Ah = gsm;
    __half* Bh = gsm + G_B_OFF;

    const int m0 = blockIdx.y * 128;
    const int n0 = blockIdx.x * 128;
    const int tid = threadIdx.x;
    const int w = tid >> 5;
    const int lane = tid & 31;
    const int grp = lane >> 2;
    const int qd = lane & 3;
    const int wm = w >> 1;
    const int wn = w & 1;

    const int rowA = (lane & 7) + (((lane >> 3) & 1) << 3);
    const int colA = (lane >> 4) << 3;

    const int ar = tid >> 1;
    const int ac = (tid & 1) * 16;
    const int am = m0 + ar;
    const int ab = am / NQ;
    const int at = am - ab * NQ;
    const int kr = tid >> 3;
    const int bc = (tid & 7) * 16;

#define OUT_PREF(kt, st)                                                       \
    do {                                                                       \
        int k = (kt) * 32 + ac;                                                \
        int hh2 = k >> 6;                                                      \
        int dd2 = k & 63;                                                      \
        uint32_t ad = smem_u32(Ah + (st) * GSA + ar * 40 + ac);                \
        const __half* ag = g_oh + (((size_t)ab * HH + hh2) * NT + at) * DD + dd2; \
        CP_A16(ad, ag, true);                                                  \
        CP_A16(ad + 16, ag + 8, true);                                         \
        uint32_t bd = smem_u32(Bh + (st) * GSB + kr * 136 + bc);               \
        const __half* bg = g_wouth + (size_t)((kt) * 32 + kr) * CDIM + n0 + bc;\
        CP_A16(bd, bg, true);                                                  \
        CP_A16(bd + 16, bg + 8, true);                                         \
    } while (0)

    float acc[2][8][4];
#pragma unroll
    for (int i = 0; i < 2; i++)
#pragma unroll
        for (int j = 0; j < 8; j++)
#pragma unroll
            for (int r = 0; r < 4; r++) acc[i][j][r] = 0.0f;

    OUT_PREF(0, 0); CP_COMMIT();
    OUT_PREF(1, 1); CP_COMMIT();

    int sc = 0;
    int sp = 2;
    for (int kt = 0; kt < 16; kt++) {
        if (kt == 15) { CP_WAIT0(); } else { CP_WAIT1(); }
        __syncthreads();
        if (kt < 14) {
            OUT_PREF(kt + 2, sp);
            CP_COMMIT();
            sp = (sp == 2) ? 0 : sp + 1;
        }
        const __half* Ac = Ah + sc * GSA;
        const __half* Bc = Bh + sc * GSB;
#pragma unroll
        for (int ks = 0; ks < 2; ks++) {
            uint32_t a[2][4];
#pragma unroll
            for (int mi = 0; mi < 2; mi++) {
                uint32_t addr = smem_u32(Ac + (wm * 32 + mi * 16 + rowA) * 40 + ks * 16 + colA);
                LDSM4(a[mi][0], a[mi][1], a[mi][2], a[mi][3], addr);
            }
#pragma unroll
            for (int nc = 0; nc < 4; nc++) {
                uint32_t b0, b1, b2, b3;
                uint32_t addr = smem_u32(Bc + (ks * 16 + rowA) * 136 + wn * 64 + nc * 16 + colA);
                LDSM4T(b0, b1, b2, b3, addr);
#pragma unroll
                for (int mi = 0; mi < 2; mi++) {
                    mma_16816(acc[mi][2 * nc],     a[mi][0], a[mi][1], a[mi][2], a[mi][3], b0, b1);
                    mma_16816(acc[mi][2 * nc + 1], a[mi][0], a[mi][1], a[mi][2], a[mi][3], b2, b3);
                }
            }
        }
        sc = (sc == 2) ? 0 : sc + 1;
    }
#undef OUT_PREF

#pragma unroll
    for (int mi = 0; mi < 2; mi++) {
        int rbase = m0 + wm * 32 + mi * 16 + grp;
#pragma unroll
        for (int rr = 0; rr < 2; rr++) {
            int m = rbase + rr * 8;
            int b = m / NQ;
            int t = m - b * NQ;
            float* orow = out + ((size_t)b * NQ + t) * CDIM;
#pragma unroll
            for (int nc = 0; nc < 8; nc++) {
                int c = n0 + wn * 64 + nc * 8 + qd * 2;
                *(float2*)(orow + c) =
                    make_float2(acc[mi][nc][rr * 2], acc[mi][nc][rr * 2 + 1]);
            }
        }
    }
}

// ---------------------------------------------------------------------------
extern "C" void kernel_launch(void* const* d_in, const int* in_sizes, int n_in,
                              void* d_out, int out_size)
{
    const float* X    = (const float*)d_in[0];   // (4,2304,512)
    const float* S    = (const float*)d_in[1];   // (4,8,512)
    const float* Wqkv = (const float*)d_in[2];   // (512,1536)
    const float* Wout = (const float*)d_in[3];   // (512,512)
    const float* temp = (const float*)d_in[4];   // (8,1,1)
    float* out = (float*)d_out;                  // (4,2304,512)

    // 0. fp32 -> fp16 conversion
    {
        int blocks = (CVT_TOT + 255) / 256;
        convert_kernel<<<blocks, 256>>>(X, S, Wqkv, Wout);
    }
    // 1. QKV GEMM + fused l2norm epilogue (3-stage ring)
    {
        (void)cudaFuncSetAttribute(qkv_mma_kernel,
                                   cudaFuncAttributeMaxDynamicSharedMemorySize,
                                   G_SMEM_BYTES);
        dim3 grid(1536 / 128, (M1 + 127) / 128);   // (12, 73)
        qkv_mma_kernel<<<grid, 256, G_SMEM_BYTES>>>();
    }
    // 2. Attention (wave-balanced 592-CTA grid; first 16 CTAs take 2 tiles)
    {
        size_t smem = (128 * 72 + 4 * KVT) * sizeof(__half);   // 55296 B
        (void)cudaFuncSetAttribute(attn_mma_kernel,
                                   cudaFuncAttributeMaxDynamicSharedMemorySize,
                                   (int)smem);
        attn_mma_kernel<<<NCTA_ATT, 256, smem>>>(temp);
    }
    // 3. Output projection (3-stage ring)
    {
        (void)cudaFuncSetAttribute(out_mma_kernel,
                                   cudaFuncAttributeMaxDynamicSharedMemorySize,
                                   G_SMEM_BYTES);
        dim3 grid(CDIM / 128, M3 / 128);           // (4, 72)
        out_mma_kernel<<<grid, 256, G_SMEM_BYTES>>>(out);
    }
}